// round 11
// baseline (speedup 1.0000x reference)
#include <cuda_runtime.h>
#include <cuda_fp16.h>
#include <math_constants.h>
#include <cstdint>

// Problem constants
#define BATCH 128
#define TLEN  256
#define CDIM  768
#define MROWS (BATCH * TLEN)     // 32768
#define HALF  (CDIM / 2)         // 384

// ---------------------------------------------------------------------------
// Device-global scratch (fp16 operands in plain k-order; ldmatrix frags)
// ---------------------------------------------------------------------------
__device__ __align__(256) __half    g_xh[(size_t)MROWS * CDIM];         // x
__device__ __align__(256) __half    g_wh[(size_t)3 * CDIM * CDIM];      // W^T [z][n][k]
__device__ __align__(256) __half    g_qo[(size_t)MROWS * CDIM];         // q (RoPE'd)
__device__ __align__(256) __half    g_ko[(size_t)MROWS * CDIM];         // k (RoPE'd)
__device__ __align__(256) __half    g_vo[(size_t)MROWS * CDIM];         // v
__device__ __align__(256) __half    g_ph[(size_t)BATCH * TLEN * TLEN];  // probs fp16
__device__ __align__(256) float     g_cos[TLEN * HALF];
__device__ __align__(256) float     g_sin[TLEN * HALF];

// ---------------------------------------------------------------------------
// Helpers
// ---------------------------------------------------------------------------
__device__ __forceinline__ uint32_t smem_u32(const void* p) {
    uint32_t a;
    asm("{ .reg .u64 t; cvta.to.shared.u64 t, %1; cvt.u32.u64 %0, t; }" : "=r"(a) : "l"(p));
    return a;
}
#define CP16(dst, src) asm volatile("cp.async.cg.shared.global [%0], [%1], 16;" :: "r"(dst), "l"(src))
#define CP_COMMIT()    asm volatile("cp.async.commit_group;" ::: "memory")
#define CP_WAIT1()     asm volatile("cp.async.wait_group 1;" ::: "memory")
#define CP_WAIT0()     asm volatile("cp.async.wait_group 0;" ::: "memory")

#define LDSM4(r0, r1, r2, r3, addr) \
    asm volatile("ldmatrix.sync.aligned.m8n8.x4.shared.b16 {%0,%1,%2,%3}, [%4];" \
        : "=r"(r0), "=r"(r1), "=r"(r2), "=r"(r3) : "r"(addr))
#define LDSM4T(r0, r1, r2, r3, addr) \
    asm volatile("ldmatrix.sync.aligned.m8n8.x4.trans.shared.b16 {%0,%1,%2,%3}, [%4];" \
        : "=r"(r0), "=r"(r1), "=r"(r2), "=r"(r3) : "r"(addr))

__device__ __forceinline__ void mma_f16(float* d, const uint32_t* a, const uint32_t* b) {
    asm volatile(
        "mma.sync.aligned.m16n8k16.row.col.f32.f16.f16.f32 "
        "{%0,%1,%2,%3}, {%4,%5,%6,%7}, {%8,%9}, {%0,%1,%2,%3};"
        : "+f"(d[0]), "+f"(d[1]), "+f"(d[2]), "+f"(d[3])
        : "r"(a[0]), "r"(a[1]), "r"(a[2]), "r"(a[3]), "r"(b[0]), "r"(b[1]));
}

// ---------------------------------------------------------------------------
// RoPE tables
// ---------------------------------------------------------------------------
__global__ void rope_table_kernel() {
    int idx = blockIdx.x * blockDim.x + threadIdx.x;
    if (idx >= TLEN * HALF) return;
    int t = idx / HALF;
    int j = idx % HALF;
    float theta = expf(-2.0f * (float)j * (1.0f / 768.0f) * 9.210340371976184f);
    float ang = (float)t * theta;
    float s, c;
    sincosf(ang, &s, &c);
    g_cos[idx] = c;
    g_sin[idx] = s;
}

// ---------------------------------------------------------------------------
// Convert x -> fp16. One thread per 8 elements.
// ---------------------------------------------------------------------------
__global__ void convert_x_fp16_kernel(const float* __restrict__ x) {
    size_t base = ((size_t)blockIdx.x * blockDim.x + threadIdx.x) * 8;
    float4 v0 = *(const float4*)(x + base);
    float4 v1 = *(const float4*)(x + base + 4);
    __half2 h[4];
    h[0] = __floats2half2_rn(v0.x, v0.y);
    h[1] = __floats2half2_rn(v0.z, v0.w);
    h[2] = __floats2half2_rn(v1.x, v1.y);
    h[3] = __floats2half2_rn(v1.z, v1.w);
    *(uint4*)(g_xh + base) = *(uint4*)h;
}

// ---------------------------------------------------------------------------
// Convert W -> W^T [n][k], fp16.
// ---------------------------------------------------------------------------
__global__ void convert_w_fp16_kernel(const float* __restrict__ Wq,
                                      const float* __restrict__ Wk,
                                      const float* __restrict__ Wv) {
    __shared__ float tile[32][33];
    int z = blockIdx.z;
    const float* W = (z == 0) ? Wq : ((z == 1) ? Wk : Wv);
    int nb = blockIdx.x * 32, kb = blockIdx.y * 32;
    int tx = threadIdx.x, ty = threadIdx.y;  // 32 x 8
#pragma unroll
    for (int r = 0; r < 32; r += 8)
        tile[ty + r][tx] = W[(size_t)(kb + ty + r) * CDIM + nb + tx];
    __syncthreads();
    __half* outw = g_wh + (size_t)z * CDIM * CDIM;
#pragma unroll
    for (int r = 0; r < 32; r += 8) {
        int n = nb + ty + r;
        outw[(size_t)n * CDIM + kb + tx] = __float2half(tile[tx][ty + r]);
    }
}

// ---------------------------------------------------------------------------
// QKV GEMM (fp16 m16n8k16 + ldmatrix, BK=64, 3-stage cp.async) — unchanged.
// ---------------------------------------------------------------------------
#define TILEB  (128 * 128)
#define STGB   (2 * TILEB)
#define NSTG   3
#define QSMEM  (NSTG * STGB)           // 98304 B
#define NKT    (CDIM / 64)             // 12

__device__ __forceinline__ void qkv_load_stage(uint32_t dst, const __half* __restrict__ gak,
                                               const __half* __restrict__ gbk, int tid) {
#pragma unroll
    for (int i = 0; i < 4; i++) {
        int cid = tid + i * 256;
        int r = cid >> 3, c = cid & 7;
        uint32_t soff = (uint32_t)(r * 128 + ((c ^ (r & 7)) << 4));
        size_t goff = (size_t)r * CDIM + c * 8;
        CP16(dst + soff, gak + goff);
        CP16(dst + TILEB + soff, gbk + goff);
    }
    CP_COMMIT();
}

__global__ void __launch_bounds__(256, 2) qkv_mma_kernel(const float* dummy) {
    extern __shared__ char smc[];
    const int z = blockIdx.y;
    const int m0 = blockIdx.z * 128;
    const int n0 = blockIdx.x * 128;
    const int tid = threadIdx.x;
    const int wid = tid >> 5, lane = tid & 31;
    const int wm = (wid & 1) * 64;
    const int wn = (wid >> 1) * 32;
    const int lr = lane >> 2, lc = lane & 3;

    const __half* __restrict__ ga = g_xh + (size_t)m0 * CDIM;
    const __half* __restrict__ gb = g_wh + (size_t)z * CDIM * CDIM + (size_t)n0 * CDIM;
    const uint32_t sbase = smem_u32(smc);

    const int l7 = lane & 7;
    const int rA = ((lane >> 3) & 1) * 8 + l7;
    const int kbitA = (lane >> 4) & 1;
    const int rB = ((lane >> 4) & 1) * 8 + l7;
    const int kbitB = (lane >> 3) & 1;

    float acc[4][4][4] = {};

    qkv_load_stage(sbase, ga, gb, tid);
    qkv_load_stage(sbase + STGB, ga + 64, gb + 64, tid);

    int cur = 0, wrt = 2;
    for (int kt = 0; kt < NKT; kt++) {
        if (kt == NKT - 1) { CP_WAIT0(); } else { CP_WAIT1(); }
        __syncthreads();

        if (kt + 2 < NKT) {
            qkv_load_stage(sbase + wrt * STGB, ga + (kt + 2) * 64, gb + (kt + 2) * 64, tid);
            wrt = (wrt == 2) ? 0 : wrt + 1;
        }

        const uint32_t As = sbase + cur * STGB;
        const uint32_t Bs = As + TILEB;
        cur = (cur == 2) ? 0 : cur + 1;

#pragma unroll
        for (int ks = 0; ks < 4; ks++) {
            uint32_t a[4][4], b[4][2];
#pragma unroll
            for (int mi = 0; mi < 4; mi++) {
                int r = wm + mi * 16 + rA;
                uint32_t addr = As + r * 128 + (((2 * ks + kbitA) ^ (r & 7)) << 4);
                LDSM4(a[mi][0], a[mi][1], a[mi][2], a[mi][3], addr);
            }
#pragma unroll
            for (int j = 0; j < 2; j++) {
                int r = wn + j * 16 + rB;
                uint32_t addr = Bs + r * 128 + (((2 * ks + kbitB) ^ (r & 7)) << 4);
                LDSM4(b[2 * j][0], b[2 * j][1], b[2 * j + 1][0], b[2 * j + 1][1], addr);
            }
#pragma unroll
            for (int mi = 0; mi < 4; mi++)
#pragma unroll
                for (int ni = 0; ni < 4; ni++)
                    mma_f16(acc[mi][ni], a[mi], b[ni]);
        }
    }

    __half* const outz = (z == 0) ? g_qo : ((z == 1) ? g_ko : g_vo);
#pragma unroll
    for (int mi = 0; mi < 4; mi++) {
#pragma unroll
        for (int half = 0; half < 2; half++) {
            int r = m0 + wm + mi * 16 + lr + half * 8;
            int t = r & (TLEN - 1);
#pragma unroll
            for (int ni = 0; ni < 4; ni++) {
                float o0 = acc[mi][ni][half * 2 + 0];
                float o1 = acc[mi][ni][half * 2 + 1];
                int c = n0 + wn + ni * 8 + 2 * lc;
                if (z < 2) {
                    int j = c >> 1;
                    float cs = g_cos[t * HALF + j], sn = g_sin[t * HALF + j];
                    float p0 = o0 * cs - o1 * sn;
                    float p1 = o0 * sn + o1 * cs;
                    o0 = p0; o1 = p1;
                }
                *(__half2*)(outz + (size_t)r * CDIM + c) = __floats2half2_rn(o0, o1);
            }
        }
    }
}

// ---------------------------------------------------------------------------
// FUSED scores + softmax. CTA = (bi, b): 64 x 256 causal band. 256 threads,
// 8 warps (2m x 4n, warp tile 32x64). Warps with wn >= jend idle; K loads
// truncated. S band in smem (64 x 264 fp32), warp-per-row softmax, fp16 P out.
// ---------------------------------------------------------------------------
#define AQ_TB   8192
#define AK_TB   32768
#define ASTGB   (AQ_TB + AK_TB)        // 40960 B per stage
#define SSTRIDE 264
#define S_OFF   (2 * ASTGB)            // 81920
#define ASMEM   (S_OFF + 64 * SSTRIDE * 4)   // 149504 B

__device__ __forceinline__ void attn_load_stage(uint32_t dst, const __half* __restrict__ gq,
                                                const __half* __restrict__ gk, int jend, int tid) {
#pragma unroll
    for (int i = 0; i < 2; i++) {
        int cid = tid + i * 256;
        int r = cid >> 3, c = cid & 7;
        uint32_t soff = (uint32_t)(r * 128 + ((c ^ (r & 7)) << 4));
        CP16(dst + soff, gq + (size_t)r * CDIM + c * 8);
    }
    const int kit = jend >> 5;
    for (int i = 0; i < kit; i++) {
        int cid = tid + i * 256;
        int r = cid >> 3, c = cid & 7;
        uint32_t soff = (uint32_t)(r * 128 + ((c ^ (r & 7)) << 4));
        CP16(dst + AQ_TB + soff, gk + (size_t)r * CDIM + c * 8);
    }
    CP_COMMIT();
}

__global__ void __launch_bounds__(256) attn_sm_kernel() {
    extern __shared__ char smc[];
    const int bi = blockIdx.x;
    const int b = blockIdx.y;
    const int jend = (bi + 1) * 64;
    const int tid = threadIdx.x;
    const int wid = tid >> 5, lane = tid & 31;
    const int wm = (wid & 1) * 32;
    const int wn = (wid >> 1) * 64;
    const int lr = lane >> 2, lc = lane & 3;
    const int l7 = lane & 7;
    const int rA = ((lane >> 3) & 1) * 8 + l7;
    const int kbitA = (lane >> 4) & 1;
    const int rB = ((lane >> 4) & 1) * 8 + l7;
    const int kbitB = (lane >> 3) & 1;
    const bool active = (wn < jend);

    const __half* __restrict__ gq = g_qo + ((size_t)b * TLEN + bi * 64) * CDIM;
    const __half* __restrict__ gk = g_ko + (size_t)b * TLEN * CDIM;
    const uint32_t sbase = smem_u32(smc);
    float* __restrict__ Ssm = (float*)(smc + S_OFF);

    float acc[2][8][4] = {};

    attn_load_stage(sbase, gq, gk, jend, tid);

    for (int kt = 0; kt < NKT; kt++) {
        if (kt + 1 < NKT) {
            attn_load_stage(sbase + ((kt + 1) & 1) * ASTGB,
                            gq + (kt + 1) * 64, gk + (kt + 1) * 64, jend, tid);
            CP_WAIT1();
        } else {
            CP_WAIT0();
        }
        __syncthreads();

        const uint32_t Qs = sbase + (kt & 1) * ASTGB;
        const uint32_t Ks = Qs + AQ_TB;

        if (active) {
#pragma unroll
            for (int ks = 0; ks < 4; ks++) {
                uint32_t a[2][4], bfr[8][2];
#pragma unroll
                for (int mi = 0; mi < 2; mi++) {
                    int r = wm + mi * 16 + rA;
                    uint32_t addr = Qs + r * 128 + (((2 * ks + kbitA) ^ (r & 7)) << 4);
                    LDSM4(a[mi][0], a[mi][1], a[mi][2], a[mi][3], addr);
                }
#pragma unroll
                for (int j = 0; j < 4; j++) {
                    int r = wn + j * 16 + rB;
                    uint32_t addr = Ks + r * 128 + (((2 * ks + kbitB) ^ (r & 7)) << 4);
                    LDSM4(bfr[2 * j][0], bfr[2 * j][1], bfr[2 * j + 1][0], bfr[2 * j + 1][1], addr);
                }
#pragma unroll
                for (int mi = 0; mi < 2; mi++)
#pragma unroll
                    for (int ni = 0; ni < 8; ni++)
                        mma_f16(acc[mi][ni], a[mi], bfr[ni]);
            }
        }
        __syncthreads();
    }

    // Write scaled S band to smem
    const float scale = 0.03608439182435161f;   // 768^-0.5
    if (active) {
#pragma unroll
        for (int mi = 0; mi < 2; mi++)
#pragma unroll
            for (int half = 0; half < 2; half++) {
                int r = wm + mi * 16 + lr + half * 8;
#pragma unroll
                for (int ni = 0; ni < 8; ni++) {
                    int c = wn + ni * 8 + 2 * lc;
                    *(float2*)(Ssm + r * SSTRIDE + c) =
                        make_float2(acc[mi][ni][half * 2] * scale,
                                    acc[mi][ni][half * 2 + 1] * scale);
                }
            }
    }
    __syncthreads();

    // Softmax: 8 rows per warp, warp-per-row over jend cols; write fp16 P.
    __half* __restrict__ prow_base = g_ph + ((size_t)b * TLEN + bi * 64) * TLEN;
    const int j0 = lane * 8;
#pragma unroll 1
    for (int rr = 0; rr < 8; rr++) {
        int r = wid * 8 + rr;
        int ig = bi * 64 + r;
        float v[8];
        if (j0 < jend) {
            float4 va = *(const float4*)(Ssm + r * SSTRIDE + j0);
            float4 vb = *(const float4*)(Ssm + r * SSTRIDE + j0 + 4);
            v[0] = va.x; v[1] = va.y; v[2] = va.z; v[3] = va.w;
            v[4] = vb.x; v[5] = vb.y; v[6] = vb.z; v[7] = vb.w;
        } else {
#pragma unroll
            for (int e = 0; e < 8; e++) v[e] = -CUDART_INF_F;
        }
        float m = -CUDART_INF_F;
#pragma unroll
        for (int e = 0; e < 8; e++) {
            if (j0 + e > ig) v[e] = -CUDART_INF_F;
            m = fmaxf(m, v[e]);
        }
#pragma unroll
        for (int off = 16; off > 0; off >>= 1)
            m = fmaxf(m, __shfl_xor_sync(0xFFFFFFFFu, m, off));
        float sum = 0.0f;
#pragma unroll
        for (int e = 0; e < 8; e++) {
            float p = expf(v[e] - m);
            v[e] = p;
            sum += p;
        }
#pragma unroll
        for (int off = 16; off > 0; off >>= 1)
            sum += __shfl_xor_sync(0xFFFFFFFFu, sum, off);
        float inv = 1.0f / sum;
        if (j0 < jend) {
            __half2 h[4];
#pragma unroll
            for (int e = 0; e < 4; e++)
                h[e] = __floats2half2_rn(v[2 * e] * inv, v[2 * e + 1] * inv);
            *(uint4*)(prow_base + (size_t)r * TLEN + j0) = *(uint4*)h;
        }
    }
}

// ---------------------------------------------------------------------------
// PV (fp16 m16n8k16; P via ldmatrix, V via ldmatrix.trans) — unchanged.
// ---------------------------------------------------------------------------
#define PTILEB (64 * 128)
#define PSTGB  (2 * PTILEB)

__device__ __forceinline__ void pv_load_stage(uint32_t dst, const __half* __restrict__ gp,
                                              const __half* __restrict__ gv, int tid) {
#pragma unroll
    for (int i = 0; i < 4; i++) {
        int cid = tid + i * 128;
        int r = cid >> 3, c = cid & 7;
        uint32_t soff = (uint32_t)(r * 128 + ((c ^ (r & 7)) << 4));
        CP16(dst + soff, gp + (size_t)r * TLEN + c * 8);
        CP16(dst + PTILEB + soff, gv + (size_t)r * CDIM + c * 8);
    }
    CP_COMMIT();
}

__global__ void __launch_bounds__(128) pv_mma_kernel(float* __restrict__ out) {
    __shared__ char smc[2 * PSTGB];
    const int bn = blockIdx.x;
    const int bm = blockIdx.y;
    const int b = blockIdx.z;

    const __half* __restrict__ gp = g_ph + ((size_t)b * TLEN + bm * 64) * TLEN;
    const __half* __restrict__ gv = g_vo + (size_t)b * TLEN * CDIM + bn * 64;
    const uint32_t sbase = smem_u32(smc);

    const int tid = threadIdx.x;
    const int wid = tid >> 5, lane = tid & 31;
    const int wm = (wid & 1) * 32;
    const int wn = (wid >> 1) * 32;
    const int lr = lane >> 2, lc = lane & 3;
    const int l7 = lane & 7;
    const int rA = ((lane >> 3) & 1) * 8 + l7;
    const int kbitA = (lane >> 4) & 1;
    const int gsel = lane >> 3;
    const int rBt = (gsel & 1) * 8 + l7;
    const int cBt = gsel >> 1;

    float acc[2][4][4] = {};
    const int nchunk = bm + 1;

    pv_load_stage(sbase, gp, gv, tid);

    for (int kt = 0; kt < nchunk; kt++) {
        if (kt + 1 < nchunk) {
            pv_load_stage(sbase + ((kt + 1) & 1) * PSTGB,
                          gp + (kt + 1) * 64, gv + (size_t)(kt + 1) * 64 * CDIM, tid);
            CP_WAIT1();
        } else {
            CP_WAIT0();
        }
        __syncthreads();

        const uint32_t Ps = sbase + (kt & 1) * PSTGB;
        const uint32_t Vs = Ps + PTILEB;

#pragma unroll
        for (int ks = 0; ks < 4; ks++) {
            uint32_t a[2][4], bfr[4][2];
#pragma unroll
            for (int mi = 0; mi < 2; mi++) {
                int r = wm + mi * 16 + rA;
                uint32_t addr = Ps + r * 128 + (((2 * ks + kbitA) ^ (r & 7)) << 4);
                LDSM4(a[mi][0], a[mi][1], a[mi][2], a[mi][3], addr);
            }
#pragma unroll
            for (int j = 0; j < 2; j++) {
                int r = ks * 16 + rBt;
                int ch = (wn >> 3) + 2 * j + cBt;
                uint32_t addr = Vs + r * 128 + ((ch ^ (r & 7)) << 4);
                LDSM4T(bfr[2 * j][0], bfr[2 * j][1], bfr[2 * j + 1][0], bfr[2 * j + 1][1], addr);
            }
#pragma unroll
            for (int mi = 0; mi < 2; mi++)
#pragma unroll
                for (int ni = 0; ni < 4; ni++)
                    mma_f16(acc[mi][ni], a[mi], bfr[ni]);
        }
        __syncthreads();
    }

    float* __restrict__ op = out + (size_t)b * TLEN * CDIM;
#pragma unroll
    for (int mi = 0; mi < 2; mi++)
#pragma unroll
        for (int half = 0; half < 2; half++) {
            int r = bm * 64 + wm + mi * 16 + lr + half * 8;
#pragma unroll
            for (int ni = 0; ni < 4; ni++) {
                int c = bn * 64 + wn + ni * 8 + 2 * lc;
                *(float2*)(op + (size_t)r * CDIM + c) =
                    make_float2(acc[mi][ni][half * 2], acc[mi][ni][half * 2 + 1]);
            }
        }
}

// ---------------------------------------------------------------------------
extern "C" void kernel_launch(void* const* d_in, const int* in_sizes, int n_in,
                              void* d_out, int out_size) {
    const float* x  = (const float*)d_in[0];
    const float* Wq = (const float*)d_in[1];
    const float* Wk = (const float*)d_in[2];
    const float* Wv = (const float*)d_in[3];
    float* out = (float*)d_out;

    cudaFuncSetAttribute(qkv_mma_kernel, cudaFuncAttributeMaxDynamicSharedMemorySize, QSMEM);
    cudaFuncSetAttribute(attn_sm_kernel, cudaFuncAttributeMaxDynamicSharedMemorySize, ASMEM);

    rope_table_kernel<<<(TLEN * HALF + 255) / 256, 256>>>();
    convert_x_fp16_kernel<<<(int)((size_t)MROWS * CDIM / 8 / 256), 256>>>(x);
    convert_w_fp16_kernel<<<dim3(CDIM / 32, CDIM / 32, 3), dim3(32, 8)>>>(Wq, Wk, Wv);
    qkv_mma_kernel<<<dim3(CDIM / 128, 3, MROWS / 128), 256, QSMEM>>>(x);
    attn_sm_kernel<<<dim3(TLEN / 64, BATCH), 256, ASMEM>>>();
    pv_mma_kernel<<<dim3(CDIM / 64, TLEN / 64, BATCH), 128>>>(out);
}

// round 14
// speedup vs baseline: 1.0397x; 1.0397x over previous
#include <cuda_runtime.h>
#include <cuda_fp16.h>
#include <math_constants.h>
#include <cstdint>

// Problem constants
#define BATCH 128
#define TLEN  256
#define CDIM  768
#define MROWS (BATCH * TLEN)     // 32768
#define HALF  (CDIM / 2)         // 384

// ---------------------------------------------------------------------------
// Device-global scratch (fp16 operands in plain k-order; ldmatrix frags)
// ---------------------------------------------------------------------------
__device__ __align__(256) __half    g_xh[(size_t)MROWS * CDIM];         // x
__device__ __align__(256) __half    g_wh[(size_t)3 * CDIM * CDIM];      // W^T [z][n][k]
__device__ __align__(256) __half    g_qo[(size_t)MROWS * CDIM];         // q (RoPE'd)
__device__ __align__(256) __half    g_ko[(size_t)MROWS * CDIM];         // k (RoPE'd)
__device__ __align__(256) __half    g_vo[(size_t)MROWS * CDIM];         // v
__device__ __align__(256) float     g_S[(size_t)BATCH * TLEN * TLEN];   // scores fp32
__device__ __align__(256) __half    g_ph[(size_t)BATCH * TLEN * TLEN];  // probs fp16
__device__ __align__(256) float     g_cos[TLEN * HALF];
__device__ __align__(256) float     g_sin[TLEN * HALF];

// ---------------------------------------------------------------------------
// Helpers
// ---------------------------------------------------------------------------
__device__ __forceinline__ uint32_t smem_u32(const void* p) {
    uint32_t a;
    asm("{ .reg .u64 t; cvta.to.shared.u64 t, %1; cvt.u32.u64 %0, t; }" : "=r"(a) : "l"(p));
    return a;
}
#define CP16(dst, src) asm volatile("cp.async.cg.shared.global [%0], [%1], 16;" :: "r"(dst), "l"(src))
#define CP_COMMIT()    asm volatile("cp.async.commit_group;" ::: "memory")
#define CP_WAIT1()     asm volatile("cp.async.wait_group 1;" ::: "memory")
#define CP_WAIT0()     asm volatile("cp.async.wait_group 0;" ::: "memory")

#define LDSM4(r0, r1, r2, r3, addr) \
    asm volatile("ldmatrix.sync.aligned.m8n8.x4.shared.b16 {%0,%1,%2,%3}, [%4];" \
        : "=r"(r0), "=r"(r1), "=r"(r2), "=r"(r3) : "r"(addr))
#define LDSM4T(r0, r1, r2, r3, addr) \
    asm volatile("ldmatrix.sync.aligned.m8n8.x4.trans.shared.b16 {%0,%1,%2,%3}, [%4];" \
        : "=r"(r0), "=r"(r1), "=r"(r2), "=r"(r3) : "r"(addr))

__device__ __forceinline__ void mma_f16(float* d, const uint32_t* a, const uint32_t* b) {
    asm volatile(
        "mma.sync.aligned.m16n8k16.row.col.f32.f16.f16.f32 "
        "{%0,%1,%2,%3}, {%4,%5,%6,%7}, {%8,%9}, {%0,%1,%2,%3};"
        : "+f"(d[0]), "+f"(d[1]), "+f"(d[2]), "+f"(d[3])
        : "r"(a[0]), "r"(a[1]), "r"(a[2]), "r"(a[3]), "r"(b[0]), "r"(b[1]));
}

// ---------------------------------------------------------------------------
// RoPE tables
// ---------------------------------------------------------------------------
__global__ void rope_table_kernel() {
    int idx = blockIdx.x * blockDim.x + threadIdx.x;
    if (idx >= TLEN * HALF) return;
    int t = idx / HALF;
    int j = idx % HALF;
    float theta = expf(-2.0f * (float)j * (1.0f / 768.0f) * 9.210340371976184f);
    float ang = (float)t * theta;
    float s, c;
    sincosf(ang, &s, &c);
    g_cos[idx] = c;
    g_sin[idx] = s;
}

// ---------------------------------------------------------------------------
// Convert x -> fp16. One thread per 8 elements.
// ---------------------------------------------------------------------------
__global__ void convert_x_fp16_kernel(const float* __restrict__ x) {
    size_t base = ((size_t)blockIdx.x * blockDim.x + threadIdx.x) * 8;
    float4 v0 = *(const float4*)(x + base);
    float4 v1 = *(const float4*)(x + base + 4);
    __half2 h[4];
    h[0] = __floats2half2_rn(v0.x, v0.y);
    h[1] = __floats2half2_rn(v0.z, v0.w);
    h[2] = __floats2half2_rn(v1.x, v1.y);
    h[3] = __floats2half2_rn(v1.z, v1.w);
    *(uint4*)(g_xh + base) = *(uint4*)h;
}

// ---------------------------------------------------------------------------
// Convert W -> W^T [n][k], fp16.
// ---------------------------------------------------------------------------
__global__ void convert_w_fp16_kernel(const float* __restrict__ Wq,
                                      const float* __restrict__ Wk,
                                      const float* __restrict__ Wv) {
    __shared__ float tile[32][33];
    int z = blockIdx.z;
    const float* W = (z == 0) ? Wq : ((z == 1) ? Wk : Wv);
    int nb = blockIdx.x * 32, kb = blockIdx.y * 32;
    int tx = threadIdx.x, ty = threadIdx.y;  // 32 x 8
#pragma unroll
    for (int r = 0; r < 32; r += 8)
        tile[ty + r][tx] = W[(size_t)(kb + ty + r) * CDIM + nb + tx];
    __syncthreads();
    __half* outw = g_wh + (size_t)z * CDIM * CDIM;
#pragma unroll
    for (int r = 0; r < 32; r += 8) {
        int n = nb + ty + r;
        outw[(size_t)n * CDIM + kb + tx] = __float2half(tile[tx][ty + r]);
    }
}

// ---------------------------------------------------------------------------
// QKV GEMM (fp16 m16n8k16 + ldmatrix, BK=64, 3-stage cp.async) — R10 verbatim.
// ---------------------------------------------------------------------------
#define TILEB  (128 * 128)
#define STGB   (2 * TILEB)
#define NSTG   3
#define QSMEM  (NSTG * STGB)           // 98304 B
#define NKT    (CDIM / 64)             // 12

__device__ __forceinline__ void qkv_load_stage(uint32_t dst, const __half* __restrict__ gak,
                                               const __half* __restrict__ gbk, int tid) {
#pragma unroll
    for (int i = 0; i < 4; i++) {
        int cid = tid + i * 256;
        int r = cid >> 3, c = cid & 7;
        uint32_t soff = (uint32_t)(r * 128 + ((c ^ (r & 7)) << 4));
        size_t goff = (size_t)r * CDIM + c * 8;
        CP16(dst + soff, gak + goff);
        CP16(dst + TILEB + soff, gbk + goff);
    }
    CP_COMMIT();
}

__global__ void __launch_bounds__(256, 2) qkv_mma_kernel(const float* dummy) {
    extern __shared__ char smc[];
    const int z = blockIdx.y;
    const int m0 = blockIdx.z * 128;
    const int n0 = blockIdx.x * 128;
    const int tid = threadIdx.x;
    const int wid = tid >> 5, lane = tid & 31;
    const int wm = (wid & 1) * 64;
    const int wn = (wid >> 1) * 32;
    const int lr = lane >> 2, lc = lane & 3;

    const __half* __restrict__ ga = g_xh + (size_t)m0 * CDIM;
    const __half* __restrict__ gb = g_wh + (size_t)z * CDIM * CDIM + (size_t)n0 * CDIM;
    const uint32_t sbase = smem_u32(smc);

    const int l7 = lane & 7;
    const int rA = ((lane >> 3) & 1) * 8 + l7;
    const int kbitA = (lane >> 4) & 1;
    const int rB = ((lane >> 4) & 1) * 8 + l7;
    const int kbitB = (lane >> 3) & 1;

    float acc[4][4][4] = {};

    qkv_load_stage(sbase, ga, gb, tid);
    qkv_load_stage(sbase + STGB, ga + 64, gb + 64, tid);

    int cur = 0, wrt = 2;
    for (int kt = 0; kt < NKT; kt++) {
        if (kt == NKT - 1) { CP_WAIT0(); } else { CP_WAIT1(); }
        __syncthreads();

        if (kt + 2 < NKT) {
            qkv_load_stage(sbase + wrt * STGB, ga + (kt + 2) * 64, gb + (kt + 2) * 64, tid);
            wrt = (wrt == 2) ? 0 : wrt + 1;
        }

        const uint32_t As = sbase + cur * STGB;
        const uint32_t Bs = As + TILEB;
        cur = (cur == 2) ? 0 : cur + 1;

#pragma unroll
        for (int ks = 0; ks < 4; ks++) {
            uint32_t a[4][4], b[4][2];
#pragma unroll
            for (int mi = 0; mi < 4; mi++) {
                int r = wm + mi * 16 + rA;
                uint32_t addr = As + r * 128 + (((2 * ks + kbitA) ^ (r & 7)) << 4);
                LDSM4(a[mi][0], a[mi][1], a[mi][2], a[mi][3], addr);
            }
#pragma unroll
            for (int j = 0; j < 2; j++) {
                int r = wn + j * 16 + rB;
                uint32_t addr = Bs + r * 128 + (((2 * ks + kbitB) ^ (r & 7)) << 4);
                LDSM4(b[2 * j][0], b[2 * j][1], b[2 * j + 1][0], b[2 * j + 1][1], addr);
            }
#pragma unroll
            for (int mi = 0; mi < 4; mi++)
#pragma unroll
                for (int ni = 0; ni < 4; ni++)
                    mma_f16(acc[mi][ni], a[mi], b[ni]);
        }
    }

    __half* const outz = (z == 0) ? g_qo : ((z == 1) ? g_ko : g_vo);
#pragma unroll
    for (int mi = 0; mi < 4; mi++) {
#pragma unroll
        for (int half = 0; half < 2; half++) {
            int r = m0 + wm + mi * 16 + lr + half * 8;
            int t = r & (TLEN - 1);
#pragma unroll
            for (int ni = 0; ni < 4; ni++) {
                float o0 = acc[mi][ni][half * 2 + 0];
                float o1 = acc[mi][ni][half * 2 + 1];
                int c = n0 + wn + ni * 8 + 2 * lc;
                if (z < 2) {
                    int j = c >> 1;
                    float cs = g_cos[t * HALF + j], sn = g_sin[t * HALF + j];
                    float p0 = o0 * cs - o1 * sn;
                    float p1 = o0 * sn + o1 * cs;
                    o0 = p0; o1 = p1;
                }
                *(__half2*)(outz + (size_t)r * CDIM + c) = __floats2half2_rn(o0, o1);
            }
        }
    }
}

// ---------------------------------------------------------------------------
// Scores (fp16 m16n8k16 + ldmatrix, BK=64, 3-stage cp.async) — R10 verbatim.
// ---------------------------------------------------------------------------
#define STILEB (64 * 128)
#define SSTGB  (2 * STILEB)
#define SSMEM  (3 * SSTGB)             // 49152 B

__device__ __forceinline__ void sc_load_stage(uint32_t dst, const __half* __restrict__ gq,
                                              const __half* __restrict__ gk, int tid) {
#pragma unroll
    for (int i = 0; i < 4; i++) {
        int cid = tid + i * 128;
        int r = cid >> 3, c = cid & 7;
        uint32_t soff = (uint32_t)(r * 128 + ((c ^ (r & 7)) << 4));
        size_t goff = (size_t)r * CDIM + c * 8;
        CP16(dst + soff, gq + goff);
        CP16(dst + STILEB + soff, gk + goff);
    }
    CP_COMMIT();
}

__global__ void __launch_bounds__(128) scores_mma_kernel() {
    __shared__ char smc[SSMEM];
    const int bj = blockIdx.x;
    const int bi = blockIdx.y;
    if (bj > bi) return;
    const int b = blockIdx.z;

    const __half* __restrict__ gq = g_qo + ((size_t)b * TLEN + bi * 64) * CDIM;
    const __half* __restrict__ gk = g_ko + ((size_t)b * TLEN + bj * 64) * CDIM;
    const uint32_t sbase = smem_u32(smc);

    const int tid = threadIdx.x;
    const int wid = tid >> 5, lane = tid & 31;
    const int wm = (wid & 1) * 32;
    const int wn = (wid >> 1) * 32;
    const int lr = lane >> 2, lc = lane & 3;
    const int l7 = lane & 7;
    const int rA = ((lane >> 3) & 1) * 8 + l7;
    const int kbitA = (lane >> 4) & 1;
    const int rB = ((lane >> 4) & 1) * 8 + l7;
    const int kbitB = (lane >> 3) & 1;

    float acc[2][4][4] = {};

    sc_load_stage(sbase, gq, gk, tid);
    sc_load_stage(sbase + SSTGB, gq + 64, gk + 64, tid);

    int cur = 0, wrt = 2;
    for (int kt = 0; kt < NKT; kt++) {
        if (kt == NKT - 1) { CP_WAIT0(); } else { CP_WAIT1(); }
        __syncthreads();

        if (kt + 2 < NKT) {
            sc_load_stage(sbase + wrt * SSTGB, gq + (kt + 2) * 64, gk + (kt + 2) * 64, tid);
            wrt = (wrt == 2) ? 0 : wrt + 1;
        }

        const uint32_t Qs = sbase + cur * SSTGB;
        const uint32_t Ks = Qs + STILEB;
        cur = (cur == 2) ? 0 : cur + 1;

#pragma unroll
        for (int ks = 0; ks < 4; ks++) {
            uint32_t a[2][4], bfr[4][2];
#pragma unroll
            for (int mi = 0; mi < 2; mi++) {
                int r = wm + mi * 16 + rA;
                uint32_t addr = Qs + r * 128 + (((2 * ks + kbitA) ^ (r & 7)) << 4);
                LDSM4(a[mi][0], a[mi][1], a[mi][2], a[mi][3], addr);
            }
#pragma unroll
            for (int j = 0; j < 2; j++) {
                int r = wn + j * 16 + rB;
                uint32_t addr = Ks + r * 128 + (((2 * ks + kbitB) ^ (r & 7)) << 4);
                LDSM4(bfr[2 * j][0], bfr[2 * j][1], bfr[2 * j + 1][0], bfr[2 * j + 1][1], addr);
            }
#pragma unroll
            for (int mi = 0; mi < 2; mi++)
#pragma unroll
                for (int ni = 0; ni < 4; ni++)
                    mma_f16(acc[mi][ni], a[mi], bfr[ni]);
        }
    }

    const float scale = 0.03608439182435161f;   // 768^-0.5
    float* __restrict__ Sp = g_S + (size_t)b * TLEN * TLEN;
#pragma unroll
    for (int mi = 0; mi < 2; mi++)
#pragma unroll
        for (int half = 0; half < 2; half++) {
            int r = bi * 64 + wm + mi * 16 + lr + half * 8;
#pragma unroll
            for (int ni = 0; ni < 4; ni++) {
                int c = bj * 64 + wn + ni * 8 + 2 * lc;
                *(float2*)(Sp + (size_t)r * TLEN + c) =
                    make_float2(acc[mi][ni][half * 2] * scale, acc[mi][ni][half * 2 + 1] * scale);
            }
        }
}

// ---------------------------------------------------------------------------
// Softmax: one warp per row; thread handles 8 contiguous j; fp16 P — R10.
// ---------------------------------------------------------------------------
__global__ void __launch_bounds__(256) softmax_kernel() {
    const int gwarp = (blockIdx.x * blockDim.x + threadIdx.x) >> 5;
    const int lane = threadIdx.x & 31;
    const int b = gwarp >> 8;
    const int i = gwarp & 255;

    const float* __restrict__ row = g_S + (size_t)b * TLEN * TLEN + (size_t)i * TLEN;
    __half* __restrict__ prow = g_ph + (size_t)b * TLEN * TLEN + (size_t)i * TLEN;

    const int j0 = lane * 8;
    float4 va = *(const float4*)(row + j0);
    float4 vb = *(const float4*)(row + j0 + 4);
    float v[8] = {va.x, va.y, va.z, va.w, vb.x, vb.y, vb.z, vb.w};

    float m = -CUDART_INF_F;
#pragma unroll
    for (int r = 0; r < 8; r++) {
        if (j0 + r > i) v[r] = -CUDART_INF_F;
        m = fmaxf(m, v[r]);
    }
#pragma unroll
    for (int off = 16; off > 0; off >>= 1)
        m = fmaxf(m, __shfl_xor_sync(0xFFFFFFFFu, m, off));

    float sum = 0.0f;
#pragma unroll
    for (int r = 0; r < 8; r++) {
        float p = expf(v[r] - m);
        v[r] = p;
        sum += p;
    }
#pragma unroll
    for (int off = 16; off > 0; off >>= 1)
        sum += __shfl_xor_sync(0xFFFFFFFFu, sum, off);

    const float inv = 1.0f / sum;
    __half2 h[4];
#pragma unroll
    for (int r = 0; r < 4; r++)
        h[r] = __floats2half2_rn(v[2 * r] * inv, v[2 * r + 1] * inv);
    *(uint4*)(prow + j0) = *(uint4*)h;
}

// ---------------------------------------------------------------------------
// PV v3: R10's PV structure verbatim, but N=128 per CTA (256 threads, 8 warps,
// warp grid 2m x 4n, warp tile 32x32). V tile rows widen to 256 B; P tile is
// shared by both n-halves (P global reads halve). grid = (6, 4, 128).
// Double-buffered: prefetch kt+1 into (kt+1)&1 at loop top (R10 discipline).
// ---------------------------------------------------------------------------
#define PV_PTB 8192                    // P tile: 64 rows x 128 B
#define PV_VTB 16384                   // V tile: 64 rows x 256 B (N=128)
#define PV_STG (PV_PTB + PV_VTB)       // 24576 B per stage
#define PV_SMEM (2 * PV_STG)           // 49152 B (static max)

__device__ __forceinline__ void pv_load_stage(uint32_t dst, const __half* __restrict__ gp,
                                              const __half* __restrict__ gv, int tid) {
    // P: 64 rows x 8 chunks = 512 chunks; 2 per thread (256 threads)
#pragma unroll
    for (int i = 0; i < 2; i++) {
        int cid = tid + i * 256;
        int r = cid >> 3, c = cid & 7;
        uint32_t soff = (uint32_t)(r * 128 + ((c ^ (r & 7)) << 4));
        CP16(dst + soff, gp + (size_t)r * TLEN + c * 8);
    }
    // V: 64 rows x 16 chunks = 1024 chunks; 4 per thread
#pragma unroll
    for (int i = 0; i < 4; i++) {
        int cid = tid + i * 256;
        int r = cid >> 4, c = cid & 15;
        uint32_t soff = (uint32_t)(r * 256 + ((c ^ (r & 7)) << 4));
        CP16(dst + PV_PTB + soff, gv + (size_t)r * CDIM + c * 8);
    }
    CP_COMMIT();
}

__global__ void __launch_bounds__(256) pv_mma_kernel(float* __restrict__ out) {
    __shared__ char smc[PV_SMEM];
    const int bn = blockIdx.x;         // n-block of 128 (0..5)
    const int bm = blockIdx.y;         // 0..3
    const int b = blockIdx.z;

    const __half* __restrict__ gp = g_ph + ((size_t)b * TLEN + bm * 64) * TLEN;
    const __half* __restrict__ gv = g_vo + (size_t)b * TLEN * CDIM + bn * 128;
    const uint32_t sbase = smem_u32(smc);

    const int tid = threadIdx.x;
    const int wid = tid >> 5, lane = tid & 31;
    const int wm = (wid & 1) * 32;
    const int wn = (wid >> 1) * 32;    // 0, 32, 64, 96
    const int lr = lane >> 2, lc = lane & 3;
    const int l7 = lane & 7;
    const int rA = ((lane >> 3) & 1) * 8 + l7;
    const int kbitA = (lane >> 4) & 1;
    const int gsel = lane >> 3;
    const int rBt = (gsel & 1) * 8 + l7;
    const int cBt = gsel >> 1;

    float acc[2][4][4] = {};
    const int nchunk = bm + 1;

    pv_load_stage(sbase, gp, gv, tid);

    for (int kt = 0; kt < nchunk; kt++) {
        if (kt + 1 < nchunk) {
            pv_load_stage(sbase + ((kt + 1) & 1) * PV_STG,
                          gp + (kt + 1) * 64, gv + (size_t)(kt + 1) * 64 * CDIM, tid);
            CP_WAIT1();
        } else {
            CP_WAIT0();
        }
        __syncthreads();

        const uint32_t Ps = sbase + (kt & 1) * PV_STG;
        const uint32_t Vs = Ps + PV_PTB;

#pragma unroll
        for (int ks = 0; ks < 4; ks++) {
            uint32_t a[2][4], bfr[4][2];
#pragma unroll
            for (int mi = 0; mi < 2; mi++) {
                int r = wm + mi * 16 + rA;
                uint32_t addr = Ps + r * 128 + (((2 * ks + kbitA) ^ (r & 7)) << 4);
                LDSM4(a[mi][0], a[mi][1], a[mi][2], a[mi][3], addr);
            }
#pragma unroll
            for (int j = 0; j < 2; j++) {
                int r = ks * 16 + rBt;
                int ch = (wn >> 3) + 2 * j + cBt;
                uint32_t addr = Vs + r * 256 + ((ch ^ (r & 7)) << 4);
                LDSM4T(bfr[2 * j][0], bfr[2 * j][1], bfr[2 * j + 1][0], bfr[2 * j + 1][1], addr);
            }
#pragma unroll
            for (int mi = 0; mi < 2; mi++)
#pragma unroll
                for (int ni = 0; ni < 4; ni++)
                    mma_f16(acc[mi][ni], a[mi], bfr[ni]);
        }
        __syncthreads();
    }

    float* __restrict__ op = out + (size_t)b * TLEN * CDIM;
#pragma unroll
    for (int mi = 0; mi < 2; mi++)
#pragma unroll
        for (int half = 0; half < 2; half++) {
            int r = bm * 64 + wm + mi * 16 + lr + half * 8;
#pragma unroll
            for (int ni = 0; ni < 4; ni++) {
                int c = bn * 128 + wn + ni * 8 + 2 * lc;
                *(float2*)(op + (size_t)r * CDIM + c) =
                    make_float2(acc[mi][ni][half * 2], acc[mi][ni][half * 2 + 1]);
            }
        }
}

// ---------------------------------------------------------------------------
extern "C" void kernel_launch(void* const* d_in, const int* in_sizes, int n_in,
                              void* d_out, int out_size) {
    const float* x  = (const float*)d_in[0];
    const float* Wq = (const float*)d_in[1];
    const float* Wk = (const float*)d_in[2];
    const float* Wv = (const float*)d_in[3];
    float* out = (float*)d_out;

    cudaFuncSetAttribute(qkv_mma_kernel, cudaFuncAttributeMaxDynamicSharedMemorySize, QSMEM);

    rope_table_kernel<<<(TLEN * HALF + 255) / 256, 256>>>();
    convert_x_fp16_kernel<<<(int)((size_t)MROWS * CDIM / 8 / 256), 256>>>(x);
    convert_w_fp16_kernel<<<dim3(CDIM / 32, CDIM / 32, 3), dim3(32, 8)>>>(Wq, Wk, Wv);
    qkv_mma_kernel<<<dim3(CDIM / 128, 3, MROWS / 128), 256, QSMEM>>>(x);
    scores_mma_kernel<<<dim3(TLEN / 64, TLEN / 64, BATCH), 128>>>();
    softmax_kernel<<<(MROWS * 32) / 256, 256>>>();
    pv_mma_kernel<<<dim3(CDIM / 128, TLEN / 64, BATCH), 256>>>(out);
}

// round 15
// speedup vs baseline: 1.0487x; 1.0087x over previous
#include <cuda_runtime.h>
#include <cuda_fp16.h>
#include <math_constants.h>
#include <cstdint>

// Problem constants
#define BATCH 128
#define TLEN  256
#define CDIM  768
#define MROWS (BATCH * TLEN)     // 32768
#define HALF  (CDIM / 2)         // 384

// ---------------------------------------------------------------------------
// Device-global scratch (fp16 operands in plain k-order; ldmatrix frags)
// ---------------------------------------------------------------------------
__device__ __align__(256) __half    g_xh[(size_t)MROWS * CDIM];         // x
__device__ __align__(256) __half    g_wh[(size_t)3 * CDIM * CDIM];      // W^T [z][n][k]
__device__ __align__(256) __half    g_qo[(size_t)MROWS * CDIM];         // q (RoPE'd)
__device__ __align__(256) __half    g_ko[(size_t)MROWS * CDIM];         // k (RoPE'd)
__device__ __align__(256) __half    g_vo[(size_t)MROWS * CDIM];         // v
__device__ __align__(256) __half    g_sh[(size_t)BATCH * TLEN * TLEN];  // scores fp16
__device__ __align__(256) __half    g_ph[(size_t)BATCH * TLEN * TLEN];  // probs fp16
__device__ __align__(256) float     g_cos[TLEN * HALF];
__device__ __align__(256) float     g_sin[TLEN * HALF];

// ---------------------------------------------------------------------------
// Helpers
// ---------------------------------------------------------------------------
__device__ __forceinline__ uint32_t smem_u32(const void* p) {
    uint32_t a;
    asm("{ .reg .u64 t; cvta.to.shared.u64 t, %1; cvt.u32.u64 %0, t; }" : "=r"(a) : "l"(p));
    return a;
}
#define CP16(dst, src) asm volatile("cp.async.cg.shared.global [%0], [%1], 16;" :: "r"(dst), "l"(src))
#define CP_COMMIT()    asm volatile("cp.async.commit_group;" ::: "memory")
#define CP_WAIT1()     asm volatile("cp.async.wait_group 1;" ::: "memory")
#define CP_WAIT0()     asm volatile("cp.async.wait_group 0;" ::: "memory")

#define LDSM4(r0, r1, r2, r3, addr) \
    asm volatile("ldmatrix.sync.aligned.m8n8.x4.shared.b16 {%0,%1,%2,%3}, [%4];" \
        : "=r"(r0), "=r"(r1), "=r"(r2), "=r"(r3) : "r"(addr))
#define LDSM4T(r0, r1, r2, r3, addr) \
    asm volatile("ldmatrix.sync.aligned.m8n8.x4.trans.shared.b16 {%0,%1,%2,%3}, [%4];" \
        : "=r"(r0), "=r"(r1), "=r"(r2), "=r"(r3) : "r"(addr))

__device__ __forceinline__ void mma_f16(float* d, const uint32_t* a, const uint32_t* b) {
    asm volatile(
        "mma.sync.aligned.m16n8k16.row.col.f32.f16.f16.f32 "
        "{%0,%1,%2,%3}, {%4,%5,%6,%7}, {%8,%9}, {%0,%1,%2,%3};"
        : "+f"(d[0]), "+f"(d[1]), "+f"(d[2]), "+f"(d[3])
        : "r"(a[0]), "r"(a[1]), "r"(a[2]), "r"(a[3]), "r"(b[0]), "r"(b[1]));
}

// ---------------------------------------------------------------------------
// RoPE tables
// ---------------------------------------------------------------------------
__global__ void rope_table_kernel() {
    int idx = blockIdx.x * blockDim.x + threadIdx.x;
    if (idx >= TLEN * HALF) return;
    int t = idx / HALF;
    int j = idx % HALF;
    float theta = expf(-2.0f * (float)j * (1.0f / 768.0f) * 9.210340371976184f);
    float ang = (float)t * theta;
    float s, c;
    sincosf(ang, &s, &c);
    g_cos[idx] = c;
    g_sin[idx] = s;
}

// ---------------------------------------------------------------------------
// Convert x -> fp16. One thread per 8 elements.
// ---------------------------------------------------------------------------
__global__ void convert_x_fp16_kernel(const float* __restrict__ x) {
    size_t base = ((size_t)blockIdx.x * blockDim.x + threadIdx.x) * 8;
    float4 v0 = *(const float4*)(x + base);
    float4 v1 = *(const float4*)(x + base + 4);
    __half2 h[4];
    h[0] = __floats2half2_rn(v0.x, v0.y);
    h[1] = __floats2half2_rn(v0.z, v0.w);
    h[2] = __floats2half2_rn(v1.x, v1.y);
    h[3] = __floats2half2_rn(v1.z, v1.w);
    *(uint4*)(g_xh + base) = *(uint4*)h;
}

// ---------------------------------------------------------------------------
// Convert W -> W^T [n][k], fp16.
// ---------------------------------------------------------------------------
__global__ void convert_w_fp16_kernel(const float* __restrict__ Wq,
                                      const float* __restrict__ Wk,
                                      const float* __restrict__ Wv) {
    __shared__ float tile[32][33];
    int z = blockIdx.z;
    const float* W = (z == 0) ? Wq : ((z == 1) ? Wk : Wv);
    int nb = blockIdx.x * 32, kb = blockIdx.y * 32;
    int tx = threadIdx.x, ty = threadIdx.y;  // 32 x 8
#pragma unroll
    for (int r = 0; r < 32; r += 8)
        tile[ty + r][tx] = W[(size_t)(kb + ty + r) * CDIM + nb + tx];
    __syncthreads();
    __half* outw = g_wh + (size_t)z * CDIM * CDIM;
#pragma unroll
    for (int r = 0; r < 32; r += 8) {
        int n = nb + ty + r;
        outw[(size_t)n * CDIM + kb + tx] = __float2half(tile[tx][ty + r]);
    }
}

// ---------------------------------------------------------------------------
// QKV GEMM (fp16 m16n8k16 + ldmatrix, BK=64, 3-stage cp.async) — R10 verbatim.
// ---------------------------------------------------------------------------
#define TILEB  (128 * 128)
#define STGB   (2 * TILEB)
#define NSTG   3
#define QSMEM  (NSTG * STGB)           // 98304 B
#define NKT    (CDIM / 64)             // 12

__device__ __forceinline__ void qkv_load_stage(uint32_t dst, const __half* __restrict__ gak,
                                               const __half* __restrict__ gbk, int tid) {
#pragma unroll
    for (int i = 0; i < 4; i++) {
        int cid = tid + i * 256;
        int r = cid >> 3, c = cid & 7;
        uint32_t soff = (uint32_t)(r * 128 + ((c ^ (r & 7)) << 4));
        size_t goff = (size_t)r * CDIM + c * 8;
        CP16(dst + soff, gak + goff);
        CP16(dst + TILEB + soff, gbk + goff);
    }
    CP_COMMIT();
}

__global__ void __launch_bounds__(256, 2) qkv_mma_kernel(const float* dummy) {
    extern __shared__ char smc[];
    const int z = blockIdx.y;
    const int m0 = blockIdx.z * 128;
    const int n0 = blockIdx.x * 128;
    const int tid = threadIdx.x;
    const int wid = tid >> 5, lane = tid & 31;
    const int wm = (wid & 1) * 64;
    const int wn = (wid >> 1) * 32;
    const int lr = lane >> 2, lc = lane & 3;

    const __half* __restrict__ ga = g_xh + (size_t)m0 * CDIM;
    const __half* __restrict__ gb = g_wh + (size_t)z * CDIM * CDIM + (size_t)n0 * CDIM;
    const uint32_t sbase = smem_u32(smc);

    const int l7 = lane & 7;
    const int rA = ((lane >> 3) & 1) * 8 + l7;
    const int kbitA = (lane >> 4) & 1;
    const int rB = ((lane >> 4) & 1) * 8 + l7;
    const int kbitB = (lane >> 3) & 1;

    float acc[4][4][4] = {};

    qkv_load_stage(sbase, ga, gb, tid);
    qkv_load_stage(sbase + STGB, ga + 64, gb + 64, tid);

    int cur = 0, wrt = 2;
    for (int kt = 0; kt < NKT; kt++) {
        if (kt == NKT - 1) { CP_WAIT0(); } else { CP_WAIT1(); }
        __syncthreads();

        if (kt + 2 < NKT) {
            qkv_load_stage(sbase + wrt * STGB, ga + (kt + 2) * 64, gb + (kt + 2) * 64, tid);
            wrt = (wrt == 2) ? 0 : wrt + 1;
        }

        const uint32_t As = sbase + cur * STGB;
        const uint32_t Bs = As + TILEB;
        cur = (cur == 2) ? 0 : cur + 1;

#pragma unroll
        for (int ks = 0; ks < 4; ks++) {
            uint32_t a[4][4], b[4][2];
#pragma unroll
            for (int mi = 0; mi < 4; mi++) {
                int r = wm + mi * 16 + rA;
                uint32_t addr = As + r * 128 + (((2 * ks + kbitA) ^ (r & 7)) << 4);
                LDSM4(a[mi][0], a[mi][1], a[mi][2], a[mi][3], addr);
            }
#pragma unroll
            for (int j = 0; j < 2; j++) {
                int r = wn + j * 16 + rB;
                uint32_t addr = Bs + r * 128 + (((2 * ks + kbitB) ^ (r & 7)) << 4);
                LDSM4(b[2 * j][0], b[2 * j][1], b[2 * j + 1][0], b[2 * j + 1][1], addr);
            }
#pragma unroll
            for (int mi = 0; mi < 4; mi++)
#pragma unroll
                for (int ni = 0; ni < 4; ni++)
                    mma_f16(acc[mi][ni], a[mi], b[ni]);
        }
    }

    __half* const outz = (z == 0) ? g_qo : ((z == 1) ? g_ko : g_vo);
#pragma unroll
    for (int mi = 0; mi < 4; mi++) {
#pragma unroll
        for (int half = 0; half < 2; half++) {
            int r = m0 + wm + mi * 16 + lr + half * 8;
            int t = r & (TLEN - 1);
#pragma unroll
            for (int ni = 0; ni < 4; ni++) {
                float o0 = acc[mi][ni][half * 2 + 0];
                float o1 = acc[mi][ni][half * 2 + 1];
                int c = n0 + wn + ni * 8 + 2 * lc;
                if (z < 2) {
                    int j = c >> 1;
                    float cs = g_cos[t * HALF + j], sn = g_sin[t * HALF + j];
                    float p0 = o0 * cs - o1 * sn;
                    float p1 = o0 * sn + o1 * cs;
                    o0 = p0; o1 = p1;
                }
                *(__half2*)(outz + (size_t)r * CDIM + c) = __floats2half2_rn(o0, o1);
            }
        }
    }
}

// ---------------------------------------------------------------------------
// Scores (fp16 m16n8k16 + ldmatrix, BK=64, 3-stage cp.async) — R10 mainloop;
// epilogue writes fp16 S (halves S traffic).
// ---------------------------------------------------------------------------
#define STILEB (64 * 128)
#define SSTGB  (2 * STILEB)
#define SSMEM  (3 * SSTGB)             // 49152 B

__device__ __forceinline__ void sc_load_stage(uint32_t dst, const __half* __restrict__ gq,
                                              const __half* __restrict__ gk, int tid) {
#pragma unroll
    for (int i = 0; i < 4; i++) {
        int cid = tid + i * 128;
        int r = cid >> 3, c = cid & 7;
        uint32_t soff = (uint32_t)(r * 128 + ((c ^ (r & 7)) << 4));
        size_t goff = (size_t)r * CDIM + c * 8;
        CP16(dst + soff, gq + goff);
        CP16(dst + STILEB + soff, gk + goff);
    }
    CP_COMMIT();
}

__global__ void __launch_bounds__(128) scores_mma_kernel() {
    __shared__ char smc[SSMEM];
    const int bj = blockIdx.x;
    const int bi = blockIdx.y;
    if (bj > bi) return;
    const int b = blockIdx.z;

    const __half* __restrict__ gq = g_qo + ((size_t)b * TLEN + bi * 64) * CDIM;
    const __half* __restrict__ gk = g_ko + ((size_t)b * TLEN + bj * 64) * CDIM;
    const uint32_t sbase = smem_u32(smc);

    const int tid = threadIdx.x;
    const int wid = tid >> 5, lane = tid & 31;
    const int wm = (wid & 1) * 32;
    const int wn = (wid >> 1) * 32;
    const int lr = lane >> 2, lc = lane & 3;
    const int l7 = lane & 7;
    const int rA = ((lane >> 3) & 1) * 8 + l7;
    const int kbitA = (lane >> 4) & 1;
    const int rB = ((lane >> 4) & 1) * 8 + l7;
    const int kbitB = (lane >> 3) & 1;

    float acc[2][4][4] = {};

    sc_load_stage(sbase, gq, gk, tid);
    sc_load_stage(sbase + SSTGB, gq + 64, gk + 64, tid);

    int cur = 0, wrt = 2;
    for (int kt = 0; kt < NKT; kt++) {
        if (kt == NKT - 1) { CP_WAIT0(); } else { CP_WAIT1(); }
        __syncthreads();

        if (kt + 2 < NKT) {
            sc_load_stage(sbase + wrt * SSTGB, gq + (kt + 2) * 64, gk + (kt + 2) * 64, tid);
            wrt = (wrt == 2) ? 0 : wrt + 1;
        }

        const uint32_t Qs = sbase + cur * SSTGB;
        const uint32_t Ks = Qs + STILEB;
        cur = (cur == 2) ? 0 : cur + 1;

#pragma unroll
        for (int ks = 0; ks < 4; ks++) {
            uint32_t a[2][4], bfr[4][2];
#pragma unroll
            for (int mi = 0; mi < 2; mi++) {
                int r = wm + mi * 16 + rA;
                uint32_t addr = Qs + r * 128 + (((2 * ks + kbitA) ^ (r & 7)) << 4);
                LDSM4(a[mi][0], a[mi][1], a[mi][2], a[mi][3], addr);
            }
#pragma unroll
            for (int j = 0; j < 2; j++) {
                int r = wn + j * 16 + rB;
                uint32_t addr = Ks + r * 128 + (((2 * ks + kbitB) ^ (r & 7)) << 4);
                LDSM4(bfr[2 * j][0], bfr[2 * j][1], bfr[2 * j + 1][0], bfr[2 * j + 1][1], addr);
            }
#pragma unroll
            for (int mi = 0; mi < 2; mi++)
#pragma unroll
                for (int ni = 0; ni < 4; ni++)
                    mma_f16(acc[mi][ni], a[mi], bfr[ni]);
        }
    }

    const float scale = 0.03608439182435161f;   // 768^-0.5
    __half* __restrict__ Sp = g_sh + (size_t)b * TLEN * TLEN;
#pragma unroll
    for (int mi = 0; mi < 2; mi++)
#pragma unroll
        for (int half = 0; half < 2; half++) {
            int r = bi * 64 + wm + mi * 16 + lr + half * 8;
#pragma unroll
            for (int ni = 0; ni < 4; ni++) {
                int c = bj * 64 + wn + ni * 8 + 2 * lc;
                *(__half2*)(Sp + (size_t)r * TLEN + c) =
                    __floats2half2_rn(acc[mi][ni][half * 2] * scale,
                                      acc[mi][ni][half * 2 + 1] * scale);
            }
        }
}

// ---------------------------------------------------------------------------
// Softmax: one warp per row; thread handles 8 contiguous j; reads fp16 S,
// fp32 math, writes fp16 P.
// ---------------------------------------------------------------------------
__global__ void __launch_bounds__(256) softmax_kernel() {
    const int gwarp = (blockIdx.x * blockDim.x + threadIdx.x) >> 5;
    const int lane = threadIdx.x & 31;
    const int b = gwarp >> 8;
    const int i = gwarp & 255;

    const __half* __restrict__ srow = g_sh + (size_t)b * TLEN * TLEN + (size_t)i * TLEN;
    __half* __restrict__ prow = g_ph + (size_t)b * TLEN * TLEN + (size_t)i * TLEN;

    const int j0 = lane * 8;
    uint4 raw = *(const uint4*)(srow + j0);
    __half2 hh[4];
    *(uint4*)hh = raw;
    float v[8];
#pragma unroll
    for (int r = 0; r < 4; r++) {
        float2 f = __half22float2(hh[r]);
        v[2 * r] = f.x;
        v[2 * r + 1] = f.y;
    }

    float m = -CUDART_INF_F;
#pragma unroll
    for (int r = 0; r < 8; r++) {
        if (j0 + r > i) v[r] = -CUDART_INF_F;
        m = fmaxf(m, v[r]);
    }
#pragma unroll
    for (int off = 16; off > 0; off >>= 1)
        m = fmaxf(m, __shfl_xor_sync(0xFFFFFFFFu, m, off));

    float sum = 0.0f;
#pragma unroll
    for (int r = 0; r < 8; r++) {
        float p = expf(v[r] - m);
        v[r] = p;
        sum += p;
    }
#pragma unroll
    for (int off = 16; off > 0; off >>= 1)
        sum += __shfl_xor_sync(0xFFFFFFFFu, sum, off);

    const float inv = 1.0f / sum;
    __half2 h[4];
#pragma unroll
    for (int r = 0; r < 4; r++)
        h[r] = __floats2half2_rn(v[2 * r] * inv, v[2 * r + 1] * inv);
    *(uint4*)(prow + j0) = *(uint4*)h;
}

// ---------------------------------------------------------------------------
// PV (fp16 m16n8k16; P via ldmatrix, V via ldmatrix.trans) — R10 verbatim.
// CTA 64x64, 128 threads, warp tile 32x32. grid = (12, 4, 128).
// ---------------------------------------------------------------------------
#define PTILEB (64 * 128)
#define PSTGB  (2 * PTILEB)

__device__ __forceinline__ void pv_load_stage(uint32_t dst, const __half* __restrict__ gp,
                                              const __half* __restrict__ gv, int tid) {
#pragma unroll
    for (int i = 0; i < 4; i++) {
        int cid = tid + i * 128;
        int r = cid >> 3, c = cid & 7;
        uint32_t soff = (uint32_t)(r * 128 + ((c ^ (r & 7)) << 4));
        CP16(dst + soff, gp + (size_t)r * TLEN + c * 8);
        CP16(dst + PTILEB + soff, gv + (size_t)r * CDIM + c * 8);
    }
    CP_COMMIT();
}

__global__ void __launch_bounds__(128) pv_mma_kernel(float* __restrict__ out) {
    __shared__ char smc[2 * PSTGB];
    const int bn = blockIdx.x;
    const int bm = blockIdx.y;
    const int b = blockIdx.z;

    const __half* __restrict__ gp = g_ph + ((size_t)b * TLEN + bm * 64) * TLEN;
    const __half* __restrict__ gv = g_vo + (size_t)b * TLEN * CDIM + bn * 64;
    const uint32_t sbase = smem_u32(smc);

    const int tid = threadIdx.x;
    const int wid = tid >> 5, lane = tid & 31;
    const int wm = (wid & 1) * 32;
    const int wn = (wid >> 1) * 32;
    const int lr = lane >> 2, lc = lane & 3;
    const int l7 = lane & 7;
    const int rA = ((lane >> 3) & 1) * 8 + l7;
    const int kbitA = (lane >> 4) & 1;
    const int gsel = lane >> 3;
    const int rBt = (gsel & 1) * 8 + l7;
    const int cBt = gsel >> 1;

    float acc[2][4][4] = {};
    const int nchunk = bm + 1;

    pv_load_stage(sbase, gp, gv, tid);

    for (int kt = 0; kt < nchunk; kt++) {
        if (kt + 1 < nchunk) {
            pv_load_stage(sbase + ((kt + 1) & 1) * PSTGB,
                          gp + (kt + 1) * 64, gv + (size_t)(kt + 1) * 64 * CDIM, tid);
            CP_WAIT1();
        } else {
            CP_WAIT0();
        }
        __syncthreads();

        const uint32_t Ps = sbase + (kt & 1) * PSTGB;
        const uint32_t Vs = Ps + PTILEB;

#pragma unroll
        for (int ks = 0; ks < 4; ks++) {
            uint32_t a[2][4], bfr[4][2];
#pragma unroll
            for (int mi = 0; mi < 2; mi++) {
                int r = wm + mi * 16 + rA;
                uint32_t addr = Ps + r * 128 + (((2 * ks + kbitA) ^ (r & 7)) << 4);
                LDSM4(a[mi][0], a[mi][1], a[mi][2], a[mi][3], addr);
            }
#pragma unroll
            for (int j = 0; j < 2; j++) {
                int r = ks * 16 + rBt;
                int ch = (wn >> 3) + 2 * j + cBt;
                uint32_t addr = Vs + r * 128 + ((ch ^ (r & 7)) << 4);
                LDSM4T(bfr[2 * j][0], bfr[2 * j][1], bfr[2 * j + 1][0], bfr[2 * j + 1][1], addr);
            }
#pragma unroll
            for (int mi = 0; mi < 2; mi++)
#pragma unroll
                for (int ni = 0; ni < 4; ni++)
                    mma_f16(acc[mi][ni], a[mi], bfr[ni]);
        }
        __syncthreads();
    }

    float* __restrict__ op = out + (size_t)b * TLEN * CDIM;
#pragma unroll
    for (int mi = 0; mi < 2; mi++)
#pragma unroll
        for (int half = 0; half < 2; half++) {
            int r = bm * 64 + wm + mi * 16 + lr + half * 8;
#pragma unroll
            for (int ni = 0; ni < 4; ni++) {
                int c = bn * 64 + wn + ni * 8 + 2 * lc;
                *(float2*)(op + (size_t)r * CDIM + c) =
                    make_float2(acc[mi][ni][half * 2], acc[mi][ni][half * 2 + 1]);
            }
        }
}

// ---------------------------------------------------------------------------
extern "C" void kernel_launch(void* const* d_in, const int* in_sizes, int n_in,
                              void* d_out, int out_size) {
    const float* x  = (const float*)d_in[0];
    const float* Wq = (const float*)d_in[1];
    const float* Wk = (const float*)d_in[2];
    const float* Wv = (const float*)d_in[3];
    float* out = (float*)d_out;

    cudaFuncSetAttribute(qkv_mma_kernel, cudaFuncAttributeMaxDynamicSharedMemorySize, QSMEM);

    rope_table_kernel<<<(TLEN * HALF + 255) / 256, 256>>>();
    convert_x_fp16_kernel<<<(int)((size_t)MROWS * CDIM / 8 / 256), 256>>>(x);
    convert_w_fp16_kernel<<<dim3(CDIM / 32, CDIM / 32, 3), dim3(32, 8)>>>(Wq, Wk, Wv);
    qkv_mma_kernel<<<dim3(CDIM / 128, 3, MROWS / 128), 256, QSMEM>>>(x);
    scores_mma_kernel<<<dim3(TLEN / 64, TLEN / 64, BATCH), 128>>>();
    softmax_kernel<<<(MROWS * 32) / 256, 256>>>();
    pv_mma_kernel<<<dim3(CDIM / 64, TLEN / 64, BATCH), 128>>>(out);
}

// round 16
// speedup vs baseline: 1.0513x; 1.0025x over previous
#include <cuda_runtime.h>
#include <cuda_fp16.h>
#include <math_constants.h>
#include <cstdint>

// Problem constants
#define BATCH 128
#define TLEN  256
#define CDIM  768
#define MROWS (BATCH * TLEN)     // 32768
#define HALF  (CDIM / 2)         // 384

// ---------------------------------------------------------------------------
// Device-global scratch (fp16 operands in plain k-order; ldmatrix frags)
// ---------------------------------------------------------------------------
__device__ __align__(256) __half    g_xh[(size_t)MROWS * CDIM];         // x
__device__ __align__(256) __half    g_wh[(size_t)3 * CDIM * CDIM];      // W^T [z][n][k]
__device__ __align__(256) __half    g_qo[(size_t)MROWS * CDIM];         // q (RoPE'd)
__device__ __align__(256) __half    g_ko[(size_t)MROWS * CDIM];         // k (RoPE'd)
__device__ __align__(256) __half    g_vo[(size_t)MROWS * CDIM];         // v
__device__ __align__(256) __half    g_sh[(size_t)BATCH * TLEN * TLEN];  // scores fp16
__device__ __align__(256) __half    g_ph[(size_t)BATCH * TLEN * TLEN];  // probs fp16
__device__ __align__(256) float     g_cos[TLEN * HALF];
__device__ __align__(256) float     g_sin[TLEN * HALF];

// ---------------------------------------------------------------------------
// Helpers
// ---------------------------------------------------------------------------
__device__ __forceinline__ uint32_t smem_u32(const void* p) {
    uint32_t a;
    asm("{ .reg .u64 t; cvta.to.shared.u64 t, %1; cvt.u32.u64 %0, t; }" : "=r"(a) : "l"(p));
    return a;
}
#define CP16(dst, src) asm volatile("cp.async.cg.shared.global [%0], [%1], 16;" :: "r"(dst), "l"(src))
#define CP_COMMIT()    asm volatile("cp.async.commit_group;" ::: "memory")
#define CP_WAIT1()     asm volatile("cp.async.wait_group 1;" ::: "memory")
#define CP_WAIT0()     asm volatile("cp.async.wait_group 0;" ::: "memory")

#define LDSM4(r0, r1, r2, r3, addr) \
    asm volatile("ldmatrix.sync.aligned.m8n8.x4.shared.b16 {%0,%1,%2,%3}, [%4];" \
        : "=r"(r0), "=r"(r1), "=r"(r2), "=r"(r3) : "r"(addr))
#define LDSM4T(r0, r1, r2, r3, addr) \
    asm volatile("ldmatrix.sync.aligned.m8n8.x4.trans.shared.b16 {%0,%1,%2,%3}, [%4];" \
        : "=r"(r0), "=r"(r1), "=r"(r2), "=r"(r3) : "r"(addr))

__device__ __forceinline__ void mma_f16(float* d, const uint32_t* a, const uint32_t* b) {
    asm volatile(
        "mma.sync.aligned.m16n8k16.row.col.f32.f16.f16.f32 "
        "{%0,%1,%2,%3}, {%4,%5,%6,%7}, {%8,%9}, {%0,%1,%2,%3};"
        : "+f"(d[0]), "+f"(d[1]), "+f"(d[2]), "+f"(d[3])
        : "r"(a[0]), "r"(a[1]), "r"(a[2]), "r"(a[3]), "r"(b[0]), "r"(b[1]));
}

// ---------------------------------------------------------------------------
// Merged prep: blocks [0, XBLK) convert x -> fp16 (8 elems/thread);
// blocks [XBLK, XBLK+ROPEBLK) fill RoPE tables. One launch instead of two.
// ---------------------------------------------------------------------------
#define XBLK    ((int)((size_t)MROWS * CDIM / 8 / 256))   // 12288
#define ROPEBLK ((TLEN * HALF + 255) / 256)               // 384

__global__ void prep_kernel(const float* __restrict__ x) {
    if (blockIdx.x < XBLK) {
        size_t base = ((size_t)blockIdx.x * blockDim.x + threadIdx.x) * 8;
        float4 v0 = *(const float4*)(x + base);
        float4 v1 = *(const float4*)(x + base + 4);
        __half2 h[4];
        h[0] = __floats2half2_rn(v0.x, v0.y);
        h[1] = __floats2half2_rn(v0.z, v0.w);
        h[2] = __floats2half2_rn(v1.x, v1.y);
        h[3] = __floats2half2_rn(v1.z, v1.w);
        *(uint4*)(g_xh + base) = *(uint4*)h;
    } else {
        int idx = (blockIdx.x - XBLK) * blockDim.x + threadIdx.x;
        if (idx >= TLEN * HALF) return;
        int t = idx / HALF;
        int j = idx % HALF;
        float theta = expf(-2.0f * (float)j * (1.0f / 768.0f) * 9.210340371976184f);
        float ang = (float)t * theta;
        float s, c;
        sincosf(ang, &s, &c);
        g_cos[idx] = c;
        g_sin[idx] = s;
    }
}

// ---------------------------------------------------------------------------
// Convert W -> W^T [n][k], fp16.
// ---------------------------------------------------------------------------
__global__ void convert_w_fp16_kernel(const float* __restrict__ Wq,
                                      const float* __restrict__ Wk,
                                      const float* __restrict__ Wv) {
    __shared__ float tile[32][33];
    int z = blockIdx.z;
    const float* W = (z == 0) ? Wq : ((z == 1) ? Wk : Wv);
    int nb = blockIdx.x * 32, kb = blockIdx.y * 32;
    int tx = threadIdx.x, ty = threadIdx.y;  // 32 x 8
#pragma unroll
    for (int r = 0; r < 32; r += 8)
        tile[ty + r][tx] = W[(size_t)(kb + ty + r) * CDIM + nb + tx];
    __syncthreads();
    __half* outw = g_wh + (size_t)z * CDIM * CDIM;
#pragma unroll
    for (int r = 0; r < 32; r += 8) {
        int n = nb + ty + r;
        outw[(size_t)n * CDIM + kb + tx] = __float2half(tile[tx][ty + r]);
    }
}

// ---------------------------------------------------------------------------
// QKV GEMM (fp16 m16n8k16 + ldmatrix, BK=64, 3-stage cp.async) — R10 verbatim.
// ---------------------------------------------------------------------------
#define TILEB  (128 * 128)
#define STGB   (2 * TILEB)
#define NSTG   3
#define QSMEM  (NSTG * STGB)           // 98304 B
#define NKT    (CDIM / 64)             // 12

__device__ __forceinline__ void qkv_load_stage(uint32_t dst, const __half* __restrict__ gak,
                                               const __half* __restrict__ gbk, int tid) {
#pragma unroll
    for (int i = 0; i < 4; i++) {
        int cid = tid + i * 256;
        int r = cid >> 3, c = cid & 7;
        uint32_t soff = (uint32_t)(r * 128 + ((c ^ (r & 7)) << 4));
        size_t goff = (size_t)r * CDIM + c * 8;
        CP16(dst + soff, gak + goff);
        CP16(dst + TILEB + soff, gbk + goff);
    }
    CP_COMMIT();
}

__global__ void __launch_bounds__(256, 2) qkv_mma_kernel(const float* dummy) {
    extern __shared__ char smc[];
    const int z = blockIdx.y;
    const int m0 = blockIdx.z * 128;
    const int n0 = blockIdx.x * 128;
    const int tid = threadIdx.x;
    const int wid = tid >> 5, lane = tid & 31;
    const int wm = (wid & 1) * 64;
    const int wn = (wid >> 1) * 32;
    const int lr = lane >> 2, lc = lane & 3;

    const __half* __restrict__ ga = g_xh + (size_t)m0 * CDIM;
    const __half* __restrict__ gb = g_wh + (size_t)z * CDIM * CDIM + (size_t)n0 * CDIM;
    const uint32_t sbase = smem_u32(smc);

    const int l7 = lane & 7;
    const int rA = ((lane >> 3) & 1) * 8 + l7;
    const int kbitA = (lane >> 4) & 1;
    const int rB = ((lane >> 4) & 1) * 8 + l7;
    const int kbitB = (lane >> 3) & 1;

    float acc[4][4][4] = {};

    qkv_load_stage(sbase, ga, gb, tid);
    qkv_load_stage(sbase + STGB, ga + 64, gb + 64, tid);

    int cur = 0, wrt = 2;
    for (int kt = 0; kt < NKT; kt++) {
        if (kt == NKT - 1) { CP_WAIT0(); } else { CP_WAIT1(); }
        __syncthreads();

        if (kt + 2 < NKT) {
            qkv_load_stage(sbase + wrt * STGB, ga + (kt + 2) * 64, gb + (kt + 2) * 64, tid);
            wrt = (wrt == 2) ? 0 : wrt + 1;
        }

        const uint32_t As = sbase + cur * STGB;
        const uint32_t Bs = As + TILEB;
        cur = (cur == 2) ? 0 : cur + 1;

#pragma unroll
        for (int ks = 0; ks < 4; ks++) {
            uint32_t a[4][4], b[4][2];
#pragma unroll
            for (int mi = 0; mi < 4; mi++) {
                int r = wm + mi * 16 + rA;
                uint32_t addr = As + r * 128 + (((2 * ks + kbitA) ^ (r & 7)) << 4);
                LDSM4(a[mi][0], a[mi][1], a[mi][2], a[mi][3], addr);
            }
#pragma unroll
            for (int j = 0; j < 2; j++) {
                int r = wn + j * 16 + rB;
                uint32_t addr = Bs + r * 128 + (((2 * ks + kbitB) ^ (r & 7)) << 4);
                LDSM4(b[2 * j][0], b[2 * j][1], b[2 * j + 1][0], b[2 * j + 1][1], addr);
            }
#pragma unroll
            for (int mi = 0; mi < 4; mi++)
#pragma unroll
                for (int ni = 0; ni < 4; ni++)
                    mma_f16(acc[mi][ni], a[mi], b[ni]);
        }
    }

    __half* const outz = (z == 0) ? g_qo : ((z == 1) ? g_ko : g_vo);
#pragma unroll
    for (int mi = 0; mi < 4; mi++) {
#pragma unroll
        for (int half = 0; half < 2; half++) {
            int r = m0 + wm + mi * 16 + lr + half * 8;
            int t = r & (TLEN - 1);
#pragma unroll
            for (int ni = 0; ni < 4; ni++) {
                float o0 = acc[mi][ni][half * 2 + 0];
                float o1 = acc[mi][ni][half * 2 + 1];
                int c = n0 + wn + ni * 8 + 2 * lc;
                if (z < 2) {
                    int j = c >> 1;
                    float cs = g_cos[t * HALF + j], sn = g_sin[t * HALF + j];
                    float p0 = o0 * cs - o1 * sn;
                    float p1 = o0 * sn + o1 * cs;
                    o0 = p0; o1 = p1;
                }
                *(__half2*)(outz + (size_t)r * CDIM + c) = __floats2half2_rn(o0, o1);
            }
        }
    }
}

// ---------------------------------------------------------------------------
// Scores (fp16 m16n8k16 + ldmatrix, BK=64, 3-stage cp.async); fp16 S out.
// ---------------------------------------------------------------------------
#define STILEB (64 * 128)
#define SSTGB  (2 * STILEB)
#define SSMEM  (3 * SSTGB)             // 49152 B

__device__ __forceinline__ void sc_load_stage(uint32_t dst, const __half* __restrict__ gq,
                                              const __half* __restrict__ gk, int tid) {
#pragma unroll
    for (int i = 0; i < 4; i++) {
        int cid = tid + i * 128;
        int r = cid >> 3, c = cid & 7;
        uint32_t soff = (uint32_t)(r * 128 + ((c ^ (r & 7)) << 4));
        size_t goff = (size_t)r * CDIM + c * 8;
        CP16(dst + soff, gq + goff);
        CP16(dst + STILEB + soff, gk + goff);
    }
    CP_COMMIT();
}

__global__ void __launch_bounds__(128) scores_mma_kernel() {
    __shared__ char smc[SSMEM];
    const int bj = blockIdx.x;
    const int bi = blockIdx.y;
    if (bj > bi) return;
    const int b = blockIdx.z;

    const __half* __restrict__ gq = g_qo + ((size_t)b * TLEN + bi * 64) * CDIM;
    const __half* __restrict__ gk = g_ko + ((size_t)b * TLEN + bj * 64) * CDIM;
    const uint32_t sbase = smem_u32(smc);

    const int tid = threadIdx.x;
    const int wid = tid >> 5, lane = tid & 31;
    const int wm = (wid & 1) * 32;
    const int wn = (wid >> 1) * 32;
    const int lr = lane >> 2, lc = lane & 3;
    const int l7 = lane & 7;
    const int rA = ((lane >> 3) & 1) * 8 + l7;
    const int kbitA = (lane >> 4) & 1;
    const int rB = ((lane >> 4) & 1) * 8 + l7;
    const int kbitB = (lane >> 3) & 1;

    float acc[2][4][4] = {};

    sc_load_stage(sbase, gq, gk, tid);
    sc_load_stage(sbase + SSTGB, gq + 64, gk + 64, tid);

    int cur = 0, wrt = 2;
    for (int kt = 0; kt < NKT; kt++) {
        if (kt == NKT - 1) { CP_WAIT0(); } else { CP_WAIT1(); }
        __syncthreads();

        if (kt + 2 < NKT) {
            sc_load_stage(sbase + wrt * SSTGB, gq + (kt + 2) * 64, gk + (kt + 2) * 64, tid);
            wrt = (wrt == 2) ? 0 : wrt + 1;
        }

        const uint32_t Qs = sbase + cur * SSTGB;
        const uint32_t Ks = Qs + STILEB;
        cur = (cur == 2) ? 0 : cur + 1;

#pragma unroll
        for (int ks = 0; ks < 4; ks++) {
            uint32_t a[2][4], bfr[4][2];
#pragma unroll
            for (int mi = 0; mi < 2; mi++) {
                int r = wm + mi * 16 + rA;
                uint32_t addr = Qs + r * 128 + (((2 * ks + kbitA) ^ (r & 7)) << 4);
                LDSM4(a[mi][0], a[mi][1], a[mi][2], a[mi][3], addr);
            }
#pragma unroll
            for (int j = 0; j < 2; j++) {
                int r = wn + j * 16 + rB;
                uint32_t addr = Ks + r * 128 + (((2 * ks + kbitB) ^ (r & 7)) << 4);
                LDSM4(bfr[2 * j][0], bfr[2 * j][1], bfr[2 * j + 1][0], bfr[2 * j + 1][1], addr);
            }
#pragma unroll
            for (int mi = 0; mi < 2; mi++)
#pragma unroll
                for (int ni = 0; ni < 4; ni++)
                    mma_f16(acc[mi][ni], a[mi], bfr[ni]);
        }
    }

    const float scale = 0.03608439182435161f;   // 768^-0.5
    __half* __restrict__ Sp = g_sh + (size_t)b * TLEN * TLEN;
#pragma unroll
    for (int mi = 0; mi < 2; mi++)
#pragma unroll
        for (int half = 0; half < 2; half++) {
            int r = bi * 64 + wm + mi * 16 + lr + half * 8;
#pragma unroll
            for (int ni = 0; ni < 4; ni++) {
                int c = bj * 64 + wn + ni * 8 + 2 * lc;
                *(__half2*)(Sp + (size_t)r * TLEN + c) =
                    __floats2half2_rn(acc[mi][ni][half * 2] * scale,
                                      acc[mi][ni][half * 2 + 1] * scale);
            }
        }
}

// ---------------------------------------------------------------------------
// Softmax: one warp per row; reads fp16 S, fp32 math, writes fp16 P.
// ---------------------------------------------------------------------------
__global__ void __launch_bounds__(256) softmax_kernel() {
    const int gwarp = (blockIdx.x * blockDim.x + threadIdx.x) >> 5;
    const int lane = threadIdx.x & 31;
    const int b = gwarp >> 8;
    const int i = gwarp & 255;

    const __half* __restrict__ srow = g_sh + (size_t)b * TLEN * TLEN + (size_t)i * TLEN;
    __half* __restrict__ prow = g_ph + (size_t)b * TLEN * TLEN + (size_t)i * TLEN;

    const int j0 = lane * 8;
    uint4 raw = *(const uint4*)(srow + j0);
    __half2 hh[4];
    *(uint4*)hh = raw;
    float v[8];
#pragma unroll
    for (int r = 0; r < 4; r++) {
        float2 f = __half22float2(hh[r]);
        v[2 * r] = f.x;
        v[2 * r + 1] = f.y;
    }

    float m = -CUDART_INF_F;
#pragma unroll
    for (int r = 0; r < 8; r++) {
        if (j0 + r > i) v[r] = -CUDART_INF_F;
        m = fmaxf(m, v[r]);
    }
#pragma unroll
    for (int off = 16; off > 0; off >>= 1)
        m = fmaxf(m, __shfl_xor_sync(0xFFFFFFFFu, m, off));

    float sum = 0.0f;
#pragma unroll
    for (int r = 0; r < 8; r++) {
        float p = expf(v[r] - m);
        v[r] = p;
        sum += p;
    }
#pragma unroll
    for (int off = 16; off > 0; off >>= 1)
        sum += __shfl_xor_sync(0xFFFFFFFFu, sum, off);

    const float inv = 1.0f / sum;
    __half2 h[4];
#pragma unroll
    for (int r = 0; r < 4; r++)
        h[r] = __floats2half2_rn(v[2 * r] * inv, v[2 * r + 1] * inv);
    *(uint4*)(prow + j0) = *(uint4*)h;
}

// ---------------------------------------------------------------------------
// PV (fp16 m16n8k16; P via ldmatrix, V via ldmatrix.trans) — R10 verbatim.
// CTA 64x64, 128 threads, warp tile 32x32. grid = (12, 4, 128).
// ---------------------------------------------------------------------------
#define PTILEB (64 * 128)
#define PSTGB  (2 * PTILEB)

__device__ __forceinline__ void pv_load_stage(uint32_t dst, const __half* __restrict__ gp,
                                              const __half* __restrict__ gv, int tid) {
#pragma unroll
    for (int i = 0; i < 4; i++) {
        int cid = tid + i * 128;
        int r = cid >> 3, c = cid & 7;
        uint32_t soff = (uint32_t)(r * 128 + ((c ^ (r & 7)) << 4));
        CP16(dst + soff, gp + (size_t)r * TLEN + c * 8);
        CP16(dst + PTILEB + soff, gv + (size_t)r * CDIM + c * 8);
    }
    CP_COMMIT();
}

__global__ void __launch_bounds__(128) pv_mma_kernel(float* __restrict__ out) {
    __shared__ char smc[2 * PSTGB];
    const int bn = blockIdx.x;
    const int bm = blockIdx.y;
    const int b = blockIdx.z;

    const __half* __restrict__ gp = g_ph + ((size_t)b * TLEN + bm * 64) * TLEN;
    const __half* __restrict__ gv = g_vo + (size_t)b * TLEN * CDIM + bn * 64;
    const uint32_t sbase = smem_u32(smc);

    const int tid = threadIdx.x;
    const int wid = tid >> 5, lane = tid & 31;
    const int wm = (wid & 1) * 32;
    const int wn = (wid >> 1) * 32;
    const int lr = lane >> 2, lc = lane & 3;
    const int l7 = lane & 7;
    const int rA = ((lane >> 3) & 1) * 8 + l7;
    const int kbitA = (lane >> 4) & 1;
    const int gsel = lane >> 3;
    const int rBt = (gsel & 1) * 8 + l7;
    const int cBt = gsel >> 1;

    float acc[2][4][4] = {};
    const int nchunk = bm + 1;

    pv_load_stage(sbase, gp, gv, tid);

    for (int kt = 0; kt < nchunk; kt++) {
        if (kt + 1 < nchunk) {
            pv_load_stage(sbase + ((kt + 1) & 1) * PSTGB,
                          gp + (kt + 1) * 64, gv + (size_t)(kt + 1) * 64 * CDIM, tid);
            CP_WAIT1();
        } else {
            CP_WAIT0();
        }
        __syncthreads();

        const uint32_t Ps = sbase + (kt & 1) * PSTGB;
        const uint32_t Vs = Ps + PTILEB;

#pragma unroll
        for (int ks = 0; ks < 4; ks++) {
            uint32_t a[2][4], bfr[4][2];
#pragma unroll
            for (int mi = 0; mi < 2; mi++) {
                int r = wm + mi * 16 + rA;
                uint32_t addr = Ps + r * 128 + (((2 * ks + kbitA) ^ (r & 7)) << 4);
                LDSM4(a[mi][0], a[mi][1], a[mi][2], a[mi][3], addr);
            }
#pragma unroll
            for (int j = 0; j < 2; j++) {
                int r = ks * 16 + rBt;
                int ch = (wn >> 3) + 2 * j + cBt;
                uint32_t addr = Vs + r * 128 + ((ch ^ (r & 7)) << 4);
                LDSM4T(bfr[2 * j][0], bfr[2 * j][1], bfr[2 * j + 1][0], bfr[2 * j + 1][1], addr);
            }
#pragma unroll
            for (int mi = 0; mi < 2; mi++)
#pragma unroll
                for (int ni = 0; ni < 4; ni++)
                    mma_f16(acc[mi][ni], a[mi], bfr[ni]);
        }
        __syncthreads();
    }

    float* __restrict__ op = out + (size_t)b * TLEN * CDIM;
#pragma unroll
    for (int mi = 0; mi < 2; mi++)
#pragma unroll
        for (int half = 0; half < 2; half++) {
            int r = bm * 64 + wm + mi * 16 + lr + half * 8;
#pragma unroll
            for (int ni = 0; ni < 4; ni++) {
                int c = bn * 64 + wn + ni * 8 + 2 * lc;
                *(float2*)(op + (size_t)r * CDIM + c) =
                    make_float2(acc[mi][ni][half * 2], acc[mi][ni][half * 2 + 1]);
            }
        }
}

// ---------------------------------------------------------------------------
extern "C" void kernel_launch(void* const* d_in, const int* in_sizes, int n_in,
                              void* d_out, int out_size) {
    const float* x  = (const float*)d_in[0];
    const float* Wq = (const float*)d_in[1];
    const float* Wk = (const float*)d_in[2];
    const float* Wv = (const float*)d_in[3];
    float* out = (float*)d_out;

    cudaFuncSetAttribute(qkv_mma_kernel, cudaFuncAttributeMaxDynamicSharedMemorySize, QSMEM);

    prep_kernel<<<XBLK + ROPEBLK, 256>>>(x);
    convert_w_fp16_kernel<<<dim3(CDIM / 32, CDIM / 32, 3), dim3(32, 8)>>>(Wq, Wk, Wv);
    qkv_mma_kernel<<<dim3(CDIM / 128, 3, MROWS / 128), 256, QSMEM>>>(x);
    scores_mma_kernel<<<dim3(TLEN / 64, TLEN / 64, BATCH), 128>>>();
    softmax_kernel<<<(MROWS * 32) / 256, 256>>>();
    pv_mma_kernel<<<dim3(CDIM / 64, TLEN / 64, BATCH), 128>>>(out);
}

// round 17
// speedup vs baseline: 1.0569x; 1.0053x over previous
#include <cuda_runtime.h>
#include <cuda_fp16.h>
#include <math_constants.h>
#include <cstdint>

// Problem constants
#define BATCH 128
#define TLEN  256
#define CDIM  768
#define MROWS (BATCH * TLEN)     // 32768
#define HALF  (CDIM / 2)         // 384

// ---------------------------------------------------------------------------
// Device-global scratch (fp16 operands in plain k-order; ldmatrix frags)
// ---------------------------------------------------------------------------
__device__ __align__(256) __half    g_xh[(size_t)MROWS * CDIM];         // x
__device__ __align__(256) __half    g_wh[(size_t)3 * CDIM * CDIM];      // W^T [z][n][k]
__device__ __align__(256) __half    g_qo[(size_t)MROWS * CDIM];         // q (RoPE'd)
__device__ __align__(256) __half    g_ko[(size_t)MROWS * CDIM];         // k (RoPE'd)
__device__ __align__(256) __half    g_vo[(size_t)MROWS * CDIM];         // v
__device__ __align__(256) __half    g_sh[(size_t)BATCH * TLEN * TLEN];  // scores fp16
__device__ __align__(256) __half    g_ph[(size_t)BATCH * TLEN * TLEN];  // probs fp16
__device__ __align__(256) float     g_cos[TLEN * HALF];
__device__ __align__(256) float     g_sin[TLEN * HALF];

// ---------------------------------------------------------------------------
// Helpers
// ---------------------------------------------------------------------------
__device__ __forceinline__ uint32_t smem_u32(const void* p) {
    uint32_t a;
    asm("{ .reg .u64 t; cvta.to.shared.u64 t, %1; cvt.u32.u64 %0, t; }" : "=r"(a) : "l"(p));
    return a;
}
#define CP16(dst, src) asm volatile("cp.async.cg.shared.global [%0], [%1], 16;" :: "r"(dst), "l"(src))
#define CP_COMMIT()    asm volatile("cp.async.commit_group;" ::: "memory")
#define CP_WAIT1()     asm volatile("cp.async.wait_group 1;" ::: "memory")
#define CP_WAIT0()     asm volatile("cp.async.wait_group 0;" ::: "memory")

#define LDSM4(r0, r1, r2, r3, addr) \
    asm volatile("ldmatrix.sync.aligned.m8n8.x4.shared.b16 {%0,%1,%2,%3}, [%4];" \
        : "=r"(r0), "=r"(r1), "=r"(r2), "=r"(r3) : "r"(addr))
#define LDSM4T(r0, r1, r2, r3, addr) \
    asm volatile("ldmatrix.sync.aligned.m8n8.x4.trans.shared.b16 {%0,%1,%2,%3}, [%4];" \
        : "=r"(r0), "=r"(r1), "=r"(r2), "=r"(r3) : "r"(addr))

__device__ __forceinline__ void mma_f16(float* d, const uint32_t* a, const uint32_t* b) {
    asm volatile(
        "mma.sync.aligned.m16n8k16.row.col.f32.f16.f16.f32 "
        "{%0,%1,%2,%3}, {%4,%5,%6,%7}, {%8,%9}, {%0,%1,%2,%3};"
        : "+f"(d[0]), "+f"(d[1]), "+f"(d[2]), "+f"(d[3])
        : "r"(a[0]), "r"(a[1]), "r"(a[2]), "r"(a[3]), "r"(b[0]), "r"(b[1]));
}

// ---------------------------------------------------------------------------
// Merged prep (ONE launch):
//   blocks [0, XBLK):                  convert x -> fp16 (8 elems/thread)
//   blocks [XBLK, XBLK+ROPEBLK):       RoPE tables
//   blocks [.., +WBLK):                convert W -> W^T fp16 (32x32 tiles)
// ---------------------------------------------------------------------------
#define XBLK    ((int)((size_t)MROWS * CDIM / 8 / 256))   // 12288
#define ROPEBLK ((TLEN * HALF + 255) / 256)               // 384
#define WTILES  ((CDIM / 32) * (CDIM / 32))               // 576 per z
#define WBLK    (3 * WTILES)                              // 1728

__global__ void prep_kernel(const float* __restrict__ x,
                            const float* __restrict__ Wq,
                            const float* __restrict__ Wk,
                            const float* __restrict__ Wv) {
    if (blockIdx.x < XBLK) {
        size_t base = ((size_t)blockIdx.x * blockDim.x + threadIdx.x) * 8;
        float4 v0 = *(const float4*)(x + base);
        float4 v1 = *(const float4*)(x + base + 4);
        __half2 h[4];
        h[0] = __floats2half2_rn(v0.x, v0.y);
        h[1] = __floats2half2_rn(v0.z, v0.w);
        h[2] = __floats2half2_rn(v1.x, v1.y);
        h[3] = __floats2half2_rn(v1.z, v1.w);
        *(uint4*)(g_xh + base) = *(uint4*)h;
    } else if (blockIdx.x < XBLK + ROPEBLK) {
        int idx = (blockIdx.x - XBLK) * blockDim.x + threadIdx.x;
        if (idx >= TLEN * HALF) return;
        int t = idx / HALF;
        int j = idx % HALF;
        float theta = expf(-2.0f * (float)j * (1.0f / 768.0f) * 9.210340371976184f);
        float ang = (float)t * theta;
        float s, c;
        sincosf(ang, &s, &c);
        g_cos[idx] = c;
        g_sin[idx] = s;
    } else {
        __shared__ float tile[32][33];
        int widx = blockIdx.x - XBLK - ROPEBLK;   // 0 .. WBLK-1
        int z = widx / WTILES;
        int rem = widx % WTILES;
        int nb = (rem % (CDIM / 32)) * 32;
        int kb = (rem / (CDIM / 32)) * 32;
        const float* W = (z == 0) ? Wq : ((z == 1) ? Wk : Wv);
        int tx = threadIdx.x & 31, ty = threadIdx.x >> 5;   // 32 x 8
#pragma unroll
        for (int r = 0; r < 32; r += 8)
            tile[ty + r][tx] = W[(size_t)(kb + ty + r) * CDIM + nb + tx];
        __syncthreads();
        __half* outw = g_wh + (size_t)z * CDIM * CDIM;
#pragma unroll
        for (int r = 0; r < 32; r += 8) {
            int n = nb + ty + r;
            outw[(size_t)n * CDIM + kb + tx] = __float2half(tile[tx][ty + r]);
        }
    }
}

// ---------------------------------------------------------------------------
// QKV GEMM (fp16 m16n8k16 + ldmatrix, BK=64, 3-stage cp.async) — unchanged.
// ---------------------------------------------------------------------------
#define TILEB  (128 * 128)
#define STGB   (2 * TILEB)
#define NSTG   3
#define QSMEM  (NSTG * STGB)           // 98304 B
#define NKT    (CDIM / 64)             // 12

__device__ __forceinline__ void qkv_load_stage(uint32_t dst, const __half* __restrict__ gak,
                                               const __half* __restrict__ gbk, int tid) {
#pragma unroll
    for (int i = 0; i < 4; i++) {
        int cid = tid + i * 256;
        int r = cid >> 3, c = cid & 7;
        uint32_t soff = (uint32_t)(r * 128 + ((c ^ (r & 7)) << 4));
        size_t goff = (size_t)r * CDIM + c * 8;
        CP16(dst + soff, gak + goff);
        CP16(dst + TILEB + soff, gbk + goff);
    }
    CP_COMMIT();
}

__global__ void __launch_bounds__(256, 2) qkv_mma_kernel(const float* dummy) {
    extern __shared__ char smc[];
    const int z = blockIdx.y;
    const int m0 = blockIdx.z * 128;
    const int n0 = blockIdx.x * 128;
    const int tid = threadIdx.x;
    const int wid = tid >> 5, lane = tid & 31;
    const int wm = (wid & 1) * 64;
    const int wn = (wid >> 1) * 32;
    const int lr = lane >> 2, lc = lane & 3;

    const __half* __restrict__ ga = g_xh + (size_t)m0 * CDIM;
    const __half* __restrict__ gb = g_wh + (size_t)z * CDIM * CDIM + (size_t)n0 * CDIM;
    const uint32_t sbase = smem_u32(smc);

    const int l7 = lane & 7;
    const int rA = ((lane >> 3) & 1) * 8 + l7;
    const int kbitA = (lane >> 4) & 1;
    const int rB = ((lane >> 4) & 1) * 8 + l7;
    const int kbitB = (lane >> 3) & 1;

    float acc[4][4][4] = {};

    qkv_load_stage(sbase, ga, gb, tid);
    qkv_load_stage(sbase + STGB, ga + 64, gb + 64, tid);

    int cur = 0, wrt = 2;
    for (int kt = 0; kt < NKT; kt++) {
        if (kt == NKT - 1) { CP_WAIT0(); } else { CP_WAIT1(); }
        __syncthreads();

        if (kt + 2 < NKT) {
            qkv_load_stage(sbase + wrt * STGB, ga + (kt + 2) * 64, gb + (kt + 2) * 64, tid);
            wrt = (wrt == 2) ? 0 : wrt + 1;
        }

        const uint32_t As = sbase + cur * STGB;
        const uint32_t Bs = As + TILEB;
        cur = (cur == 2) ? 0 : cur + 1;

#pragma unroll
        for (int ks = 0; ks < 4; ks++) {
            uint32_t a[4][4], b[4][2];
#pragma unroll
            for (int mi = 0; mi < 4; mi++) {
                int r = wm + mi * 16 + rA;
                uint32_t addr = As + r * 128 + (((2 * ks + kbitA) ^ (r & 7)) << 4);
                LDSM4(a[mi][0], a[mi][1], a[mi][2], a[mi][3], addr);
            }
#pragma unroll
            for (int j = 0; j < 2; j++) {
                int r = wn + j * 16 + rB;
                uint32_t addr = Bs + r * 128 + (((2 * ks + kbitB) ^ (r & 7)) << 4);
                LDSM4(b[2 * j][0], b[2 * j][1], b[2 * j + 1][0], b[2 * j + 1][1], addr);
            }
#pragma unroll
            for (int mi = 0; mi < 4; mi++)
#pragma unroll
                for (int ni = 0; ni < 4; ni++)
                    mma_f16(acc[mi][ni], a[mi], b[ni]);
        }
    }

    __half* const outz = (z == 0) ? g_qo : ((z == 1) ? g_ko : g_vo);
#pragma unroll
    for (int mi = 0; mi < 4; mi++) {
#pragma unroll
        for (int half = 0; half < 2; half++) {
            int r = m0 + wm + mi * 16 + lr + half * 8;
            int t = r & (TLEN - 1);
#pragma unroll
            for (int ni = 0; ni < 4; ni++) {
                float o0 = acc[mi][ni][half * 2 + 0];
                float o1 = acc[mi][ni][half * 2 + 1];
                int c = n0 + wn + ni * 8 + 2 * lc;
                if (z < 2) {
                    int j = c >> 1;
                    float cs = g_cos[t * HALF + j], sn = g_sin[t * HALF + j];
                    float p0 = o0 * cs - o1 * sn;
                    float p1 = o0 * sn + o1 * cs;
                    o0 = p0; o1 = p1;
                }
                *(__half2*)(outz + (size_t)r * CDIM + c) = __floats2half2_rn(o0, o1);
            }
        }
    }
}

// ---------------------------------------------------------------------------
// Scores (fp16 m16n8k16 + ldmatrix, BK=64, 3-stage cp.async); fp16 S out.
// ---------------------------------------------------------------------------
#define STILEB (64 * 128)
#define SSTGB  (2 * STILEB)
#define SSMEM  (3 * SSTGB)             // 49152 B

__device__ __forceinline__ void sc_load_stage(uint32_t dst, const __half* __restrict__ gq,
                                              const __half* __restrict__ gk, int tid) {
#pragma unroll
    for (int i = 0; i < 4; i++) {
        int cid = tid + i * 128;
        int r = cid >> 3, c = cid & 7;
        uint32_t soff = (uint32_t)(r * 128 + ((c ^ (r & 7)) << 4));
        size_t goff = (size_t)r * CDIM + c * 8;
        CP16(dst + soff, gq + goff);
        CP16(dst + STILEB + soff, gk + goff);
    }
    CP_COMMIT();
}

__global__ void __launch_bounds__(128) scores_mma_kernel() {
    __shared__ char smc[SSMEM];
    const int bj = blockIdx.x;
    const int bi = blockIdx.y;
    if (bj > bi) return;
    const int b = blockIdx.z;

    const __half* __restrict__ gq = g_qo + ((size_t)b * TLEN + bi * 64) * CDIM;
    const __half* __restrict__ gk = g_ko + ((size_t)b * TLEN + bj * 64) * CDIM;
    const uint32_t sbase = smem_u32(smc);

    const int tid = threadIdx.x;
    const int wid = tid >> 5, lane = tid & 31;
    const int wm = (wid & 1) * 32;
    const int wn = (wid >> 1) * 32;
    const int lr = lane >> 2, lc = lane & 3;
    const int l7 = lane & 7;
    const int rA = ((lane >> 3) & 1) * 8 + l7;
    const int kbitA = (lane >> 4) & 1;
    const int rB = ((lane >> 4) & 1) * 8 + l7;
    const int kbitB = (lane >> 3) & 1;

    float acc[2][4][4] = {};

    sc_load_stage(sbase, gq, gk, tid);
    sc_load_stage(sbase + SSTGB, gq + 64, gk + 64, tid);

    int cur = 0, wrt = 2;
    for (int kt = 0; kt < NKT; kt++) {
        if (kt == NKT - 1) { CP_WAIT0(); } else { CP_WAIT1(); }
        __syncthreads();

        if (kt + 2 < NKT) {
            sc_load_stage(sbase + wrt * SSTGB, gq + (kt + 2) * 64, gk + (kt + 2) * 64, tid);
            wrt = (wrt == 2) ? 0 : wrt + 1;
        }

        const uint32_t Qs = sbase + cur * SSTGB;
        const uint32_t Ks = Qs + STILEB;
        cur = (cur == 2) ? 0 : cur + 1;

#pragma unroll
        for (int ks = 0; ks < 4; ks++) {
            uint32_t a[2][4], bfr[4][2];
#pragma unroll
            for (int mi = 0; mi < 2; mi++) {
                int r = wm + mi * 16 + rA;
                uint32_t addr = Qs + r * 128 + (((2 * ks + kbitA) ^ (r & 7)) << 4);
                LDSM4(a[mi][0], a[mi][1], a[mi][2], a[mi][3], addr);
            }
#pragma unroll
            for (int j = 0; j < 2; j++) {
                int r = wn + j * 16 + rB;
                uint32_t addr = Ks + r * 128 + (((2 * ks + kbitB) ^ (r & 7)) << 4);
                LDSM4(bfr[2 * j][0], bfr[2 * j][1], bfr[2 * j + 1][0], bfr[2 * j + 1][1], addr);
            }
#pragma unroll
            for (int mi = 0; mi < 2; mi++)
#pragma unroll
                for (int ni = 0; ni < 4; ni++)
                    mma_f16(acc[mi][ni], a[mi], bfr[ni]);
        }
    }

    const float scale = 0.03608439182435161f;   // 768^-0.5
    __half* __restrict__ Sp = g_sh + (size_t)b * TLEN * TLEN;
#pragma unroll
    for (int mi = 0; mi < 2; mi++)
#pragma unroll
        for (int half = 0; half < 2; half++) {
            int r = bi * 64 + wm + mi * 16 + lr + half * 8;
#pragma unroll
            for (int ni = 0; ni < 4; ni++) {
                int c = bj * 64 + wn + ni * 8 + 2 * lc;
                *(__half2*)(Sp + (size_t)r * TLEN + c) =
                    __floats2half2_rn(acc[mi][ni][half * 2] * scale,
                                      acc[mi][ni][half * 2 + 1] * scale);
            }
        }
}

// ---------------------------------------------------------------------------
// Softmax: one warp per row; reads fp16 S, fp32 math, writes fp16 P.
// ---------------------------------------------------------------------------
__global__ void __launch_bounds__(256) softmax_kernel() {
    const int gwarp = (blockIdx.x * blockDim.x + threadIdx.x) >> 5;
    const int lane = threadIdx.x & 31;
    const int b = gwarp >> 8;
    const int i = gwarp & 255;

    const __half* __restrict__ srow = g_sh + (size_t)b * TLEN * TLEN + (size_t)i * TLEN;
    __half* __restrict__ prow = g_ph + (size_t)b * TLEN * TLEN + (size_t)i * TLEN;

    const int j0 = lane * 8;
    uint4 raw = *(const uint4*)(srow + j0);
    __half2 hh[4];
    *(uint4*)hh = raw;
    float v[8];
#pragma unroll
    for (int r = 0; r < 4; r++) {
        float2 f = __half22float2(hh[r]);
        v[2 * r] = f.x;
        v[2 * r + 1] = f.y;
    }

    float m = -CUDART_INF_F;
#pragma unroll
    for (int r = 0; r < 8; r++) {
        if (j0 + r > i) v[r] = -CUDART_INF_F;
        m = fmaxf(m, v[r]);
    }
#pragma unroll
    for (int off = 16; off > 0; off >>= 1)
        m = fmaxf(m, __shfl_xor_sync(0xFFFFFFFFu, m, off));

    float sum = 0.0f;
#pragma unroll
    for (int r = 0; r < 8; r++) {
        float p = expf(v[r] - m);
        v[r] = p;
        sum += p;
    }
#pragma unroll
    for (int off = 16; off > 0; off >>= 1)
        sum += __shfl_xor_sync(0xFFFFFFFFu, sum, off);

    const float inv = 1.0f / sum;
    __half2 h[4];
#pragma unroll
    for (int r = 0; r < 4; r++)
        h[r] = __floats2half2_rn(v[2 * r] * inv, v[2 * r + 1] * inv);
    *(uint4*)(prow + j0) = *(uint4*)h;
}

// ---------------------------------------------------------------------------
// PV (fp16 m16n8k16; P via ldmatrix, V via ldmatrix.trans) — unchanged.
// CTA 64x64, 128 threads, warp tile 32x32. grid = (12, 4, 128).
// ---------------------------------------------------------------------------
#define PTILEB (64 * 128)
#define PSTGB  (2 * PTILEB)

__device__ __forceinline__ void pv_load_stage(uint32_t dst, const __half* __restrict__ gp,
                                              const __half* __restrict__ gv, int tid) {
#pragma unroll
    for (int i = 0; i < 4; i++) {
        int cid = tid + i * 128;
        int r = cid >> 3, c = cid & 7;
        uint32_t soff = (uint32_t)(r * 128 + ((c ^ (r & 7)) << 4));
        CP16(dst + soff, gp + (size_t)r * TLEN + c * 8);
        CP16(dst + PTILEB + soff, gv + (size_t)r * CDIM + c * 8);
    }
    CP_COMMIT();
}

__global__ void __launch_bounds__(128) pv_mma_kernel(float* __restrict__ out) {
    __shared__ char smc[2 * PSTGB];
    const int bn = blockIdx.x;
    const int bm = blockIdx.y;
    const int b = blockIdx.z;

    const __half* __restrict__ gp = g_ph + ((size_t)b * TLEN + bm * 64) * TLEN;
    const __half* __restrict__ gv = g_vo + (size_t)b * TLEN * CDIM + bn * 64;
    const uint32_t sbase = smem_u32(smc);

    const int tid = threadIdx.x;
    const int wid = tid >> 5, lane = tid & 31;
    const int wm = (wid & 1) * 32;
    const int wn = (wid >> 1) * 32;
    const int lr = lane >> 2, lc = lane & 3;
    const int l7 = lane & 7;
    const int rA = ((lane >> 3) & 1) * 8 + l7;
    const int kbitA = (lane >> 4) & 1;
    const int gsel = lane >> 3;
    const int rBt = (gsel & 1) * 8 + l7;
    const int cBt = gsel >> 1;

    float acc[2][4][4] = {};
    const int nchunk = bm + 1;

    pv_load_stage(sbase, gp, gv, tid);

    for (int kt = 0; kt < nchunk; kt++) {
        if (kt + 1 < nchunk) {
            pv_load_stage(sbase + ((kt + 1) & 1) * PSTGB,
                          gp + (kt + 1) * 64, gv + (size_t)(kt + 1) * 64 * CDIM, tid);
            CP_WAIT1();
        } else {
            CP_WAIT0();
        }
        __syncthreads();

        const uint32_t Ps = sbase + (kt & 1) * PSTGB;
        const uint32_t Vs = Ps + PTILEB;

#pragma unroll
        for (int ks = 0; ks < 4; ks++) {
            uint32_t a[2][4], bfr[4][2];
#pragma unroll
            for (int mi = 0; mi < 2; mi++) {
                int r = wm + mi * 16 + rA;
                uint32_t addr = Ps + r * 128 + (((2 * ks + kbitA) ^ (r & 7)) << 4);
                LDSM4(a[mi][0], a[mi][1], a[mi][2], a[mi][3], addr);
            }
#pragma unroll
            for (int j = 0; j < 2; j++) {
                int r = ks * 16 + rBt;
                int ch = (wn >> 3) + 2 * j + cBt;
                uint32_t addr = Vs + r * 128 + ((ch ^ (r & 7)) << 4);
                LDSM4T(bfr[2 * j][0], bfr[2 * j][1], bfr[2 * j + 1][0], bfr[2 * j + 1][1], addr);
            }
#pragma unroll
            for (int mi = 0; mi < 2; mi++)
#pragma unroll
                for (int ni = 0; ni < 4; ni++)
                    mma_f16(acc[mi][ni], a[mi], bfr[ni]);
        }
        __syncthreads();
    }

    float* __restrict__ op = out + (size_t)b * TLEN * CDIM;
#pragma unroll
    for (int mi = 0; mi < 2; mi++)
#pragma unroll
        for (int half = 0; half < 2; half++) {
            int r = bm * 64 + wm + mi * 16 + lr + half * 8;
#pragma unroll
            for (int ni = 0; ni < 4; ni++) {
                int c = bn * 64 + wn + ni * 8 + 2 * lc;
                *(float2*)(op + (size_t)r * CDIM + c) =
                    make_float2(acc[mi][ni][half * 2], acc[mi][ni][half * 2 + 1]);
            }
        }
}

// ---------------------------------------------------------------------------
extern "C" void kernel_launch(void* const* d_in, const int* in_sizes, int n_in,
                              void* d_out, int out_size) {
    const float* x  = (const float*)d_in[0];
    const float* Wq = (const float*)d_in[1];
    const float* Wk = (const float*)d_in[2];
    const float* Wv = (const float*)d_in[3];
    float* out = (float*)d_out;

    cudaFuncSetAttribute(qkv_mma_kernel, cudaFuncAttributeMaxDynamicSharedMemorySize, QSMEM);

    prep_kernel<<<XBLK + ROPEBLK + WBLK, 256>>>(x, Wq, Wk, Wv);
    qkv_mma_kernel<<<dim3(CDIM / 128, 3, MROWS / 128), 256, QSMEM>>>(x);
    scores_mma_kernel<<<dim3(TLEN / 64, TLEN / 64, BATCH), 128>>>();
    softmax_kernel<<<(MROWS * 32) / 256, 256>>>();
    pv_mma_kernel<<<dim3(CDIM / 64, TLEN / 64, BATCH), 128>>>(out);
}